// round 12
// baseline (speedup 1.0000x reference)
#include <cuda_runtime.h>
#include <cuda_fp16.h>
#include <math.h>
#include <stdint.h>

#define BATCH 2
#define NTOK  2048
#define HEADS 24
#define DHEAD 128
#define CM    3072
#define MTOT  (BATCH*NTOK)   // 4096

// fp32 scratch — used only by the non-'a' fallback path.
__device__ __align__(256) float g_q[(size_t)BATCH*HEADS*NTOK*DHEAD];
__device__ __align__(256) float g_k[(size_t)BATCH*HEADS*NTOK*DHEAD];
// fp16 scratch
__device__ __align__(256) __half g_x16[(size_t)MTOT*CM];
__device__ __align__(256) __half g_w16[(size_t)3*CM*CM];
__device__ __align__(256) __half g_pw16[(size_t)CM*CM];
__device__ __align__(256) __half g_q16[(size_t)BATCH*HEADS*NTOK*DHEAD];
__device__ __align__(256) __half g_k16[(size_t)BATCH*HEADS*NTOK*DHEAD];
__device__ __align__(256) __half g_v16[(size_t)BATCH*HEADS*NTOK*DHEAD];
__device__ __align__(256) __half g_att16[(size_t)MTOT*CM];
// RoPE cos/sin table: [tok][pair]
__device__ __align__(256) float2 g_rtab[(size_t)NTOK*64];

// ---------------------------------------------------------------------------
// base-ISA helpers
// ---------------------------------------------------------------------------
__device__ __forceinline__ uint32_t smaddr(const void* p) {
    return (uint32_t)__cvta_generic_to_shared(p);
}
__device__ __forceinline__ void ldsm4(uint32_t& r0, uint32_t& r1, uint32_t& r2,
                                      uint32_t& r3, uint32_t a) {
    asm volatile("ldmatrix.sync.aligned.m8n8.x4.shared.b16 {%0,%1,%2,%3},[%4];"
                 : "=r"(r0), "=r"(r1), "=r"(r2), "=r"(r3) : "r"(a));
}
__device__ __forceinline__ void ldsm4t(uint32_t& r0, uint32_t& r1, uint32_t& r2,
                                       uint32_t& r3, uint32_t a) {
    asm volatile("ldmatrix.sync.aligned.m8n8.x4.trans.shared.b16 {%0,%1,%2,%3},[%4];"
                 : "=r"(r0), "=r"(r1), "=r"(r2), "=r"(r3) : "r"(a));
}
__device__ __forceinline__ void mma16(float c[4], const uint32_t a[4], const uint32_t b[2]) {
    asm volatile("mma.sync.aligned.m16n8k16.row.col.f32.f16.f16.f32 "
                 "{%0,%1,%2,%3},{%4,%5,%6,%7},{%8,%9},{%0,%1,%2,%3};"
                 : "+f"(c[0]), "+f"(c[1]), "+f"(c[2]), "+f"(c[3])
                 : "r"(a[0]), "r"(a[1]), "r"(a[2]), "r"(a[3]), "r"(b[0]), "r"(b[1]));
}
__device__ __forceinline__ void cpa16(uint32_t s, const void* g) {
    asm volatile("cp.async.cg.shared.global [%0],[%1],16;" :: "r"(s), "l"(g));
}
#define CP_COMMIT() asm volatile("cp.async.commit_group;")
#define CP_WAIT(n)  asm volatile("cp.async.wait_group %0;" :: "n"(n))
__device__ __forceinline__ uint32_t h2u(float lo, float hi) {
    __half2 h = __floats2half2_rn(lo, hi);
    return *(uint32_t*)&h;
}
__device__ __forceinline__ void mbar_init(uint32_t a, uint32_t c) {
    asm volatile("mbarrier.init.shared.b64 [%0], %1;" :: "r"(a), "r"(c) : "memory");
}
__device__ __forceinline__ void mbar_wait(uint32_t mbar, uint32_t parity) {
    asm volatile("{\n\t.reg .pred P1;\n\t"
                 "W_%=:\n\t"
                 "mbarrier.try_wait.parity.acquire.cta.shared::cta.b64 P1, [%0], %1, 0x989680;\n\t"
                 "@P1 bra.uni D_%=;\n\t"
                 "bra.uni W_%=;\n\t"
                 "D_%=:\n\t}" :: "r"(mbar), "r"(parity) : "memory");
}
__device__ __forceinline__ void mbar_arrive_local(uint32_t a) {
    asm volatile("mbarrier.arrive.shared.b64 _, [%0];" :: "r"(a) : "memory");
}
__device__ __forceinline__ void mbar_arrive_cluster_rank(uint32_t a, uint32_t rk) {
    asm volatile("{\n\t.reg .b32 ra;\n\t"
                 "mapa.shared::cluster.u32 ra, %0, %1;\n\t"
                 "mbarrier.arrive.shared::cluster.b64 _, [ra];\n\t}"
                 :: "r"(a), "r"(rk) : "memory");
}
#define CLUSTER_ARRIVE() asm volatile("barrier.cluster.arrive.aligned;" ::: "memory")
#define CLUSTER_WAIT()   asm volatile("barrier.cluster.wait.aligned;"   ::: "memory")
__device__ __forceinline__ uint32_t ctarank() {
    uint32_t r; asm("mov.u32 %0, %%cluster_ctarank;" : "=r"(r)); return r;
}

#define SMEM_SWIZZLE_128B(o) ((o) ^ (((o) >> 3) & 0x70))

// ---------------------------------------------------------------------------
// tcgen05 helpers — sm_103a ('a' feature) pass only.
// ---------------------------------------------------------------------------
#if defined(__CUDA_ARCH_FEAT_SM103_ALL) || defined(__CUDA_ARCH_FEAT_SM100_ALL)
#define TC_ON 1
static constexpr uint64_t SMEM_DESC_BASE_SW128 =
    (uint64_t(2)  << 61) | (uint64_t(1) << 46) | (uint64_t(64) << 32) | (uint64_t(1) << 16);
__device__ __forceinline__ uint64_t mk_desc(uint32_t a) {
    return SMEM_DESC_BASE_SW128 | ((uint64_t)(a >> 4) & 0x3FFF);
}
__device__ __forceinline__ void mma_f16_ss_cg2(uint32_t d, uint64_t ad, uint64_t bd,
                                               uint32_t idesc, bool acc) {
    uint32_t en = acc ? 1u : 0u;
    asm volatile("{\n\t.reg .pred p;\n\tsetp.ne.u32 p, %4, 0;\n\t"
                 "tcgen05.mma.cta_group::2.kind::f16 [%0], %1, %2, %3, "
                 "{%5,%5,%5,%5,%5,%5,%5,%5}, p;\n\t}"
                 :: "r"(d), "l"(ad), "l"(bd), "r"(idesc), "r"(en), "r"(0u) : "memory");
}
__device__ __forceinline__ void tc_commit_mc2(uint32_t mbar) {
    asm volatile("tcgen05.commit.cta_group::2.mbarrier::arrive::one.shared::cluster"
                 ".multicast::cluster.b64 [%0], %1;"
                 :: "r"(mbar), "h"((uint16_t)0x3) : "memory");
}
#define LDTM_X32(r, addr) \
    asm volatile("tcgen05.ld.sync.aligned.32x32b.x32.b32 " \
        "{%0,%1,%2,%3,%4,%5,%6,%7,%8,%9,%10,%11,%12,%13,%14,%15," \
        "%16,%17,%18,%19,%20,%21,%22,%23,%24,%25,%26,%27,%28,%29,%30,%31},[%32];" \
        : "=r"((r)[0]),"=r"((r)[1]),"=r"((r)[2]),"=r"((r)[3]), \
          "=r"((r)[4]),"=r"((r)[5]),"=r"((r)[6]),"=r"((r)[7]), \
          "=r"((r)[8]),"=r"((r)[9]),"=r"((r)[10]),"=r"((r)[11]), \
          "=r"((r)[12]),"=r"((r)[13]),"=r"((r)[14]),"=r"((r)[15]), \
          "=r"((r)[16]),"=r"((r)[17]),"=r"((r)[18]),"=r"((r)[19]), \
          "=r"((r)[20]),"=r"((r)[21]),"=r"((r)[22]),"=r"((r)[23]), \
          "=r"((r)[24]),"=r"((r)[25]),"=r"((r)[26]),"=r"((r)[27]), \
          "=r"((r)[28]),"=r"((r)[29]),"=r"((r)[30]),"=r"((r)[31]) \
        : "r"(addr))
#endif

// ---------------------------------------------------------------------------
// fp32 -> fp16 converter
// ---------------------------------------------------------------------------
__global__ void f2h_kernel(const float4* __restrict__ src, uint4* __restrict__ dst,
                           int n8)
{
    for (int i = blockIdx.x * blockDim.x + threadIdx.x; i < n8;
         i += gridDim.x * blockDim.x) {
        float4 a = src[2 * i], b = src[2 * i + 1];
        dst[i] = make_uint4(h2u(a.x, a.y), h2u(a.z, a.w), h2u(b.x, b.y), h2u(b.z, b.w));
    }
}

// ---------------------------------------------------------------------------
// RoPE table
// ---------------------------------------------------------------------------
__global__ void rope_tab_kernel()
{
    int idx = blockIdx.x * 64 + threadIdx.x;
    int tok = idx >> 6, p = idx & 63;
    int d = 2 * p;
    float pos, e;
    if (d < 44)      { pos = (float)(tok >> 8);        e = (float)d        * (1.f / 44.f); }
    else if (d < 86) { pos = (float)((tok >> 4) & 15); e = (float)(d - 44) * (1.f / 42.f); }
    else             { pos = (float)(tok & 15);        e = (float)(d - 86) * (1.f / 42.f); }
    float f = expf(-9.210340371976184f * e);
    float cs, sn;
    sincosf(pos * f, &sn, &cs);
    g_rtab[idx] = make_float2(cs, sn);
}

// ---------------------------------------------------------------------------
// Unified GEMM-NT (cg2): C[m,n] = sum_k A[m,k]*B[n,k] + bias[n], K = 3072.
// Grid (2, N/256, M/256), cluster (2,1,1): the two x-blocks of each (y,z)
// form one pair computing a 256x256 tile (M split by rank for A/D, N split
// by rank for B — exactly the test_2cta_mma_bf16 convention).
// Per-CTA per stage: own 128 A rows + own 128 B rows = 32 KB (1.5x less
// fill traffic than cg1). Ready-mbar(count=2) gates rank0's MMA issue;
// commit-multicast done-mbar gates refills per CTA. One cp.async commit
// group per mainloop iter; CP_WAIT(2) retires chunk ks (proven ledger).
// MODE 0: fp32 C. MODE 1: QKV epilogue with fused rope/rms (q,k), bias (v).
// ---------------------------------------------------------------------------
#define TSTAGE  32768            // A 16KB + B 16KB per stage
#define TAB     16384
#define GEMM_SMEM (3072 + 4 * TSTAGE)   // 134144 B

template<int MODE>
__global__ __launch_bounds__(256, 1) __cluster_dims__(2, 1, 1)
void gemm_u(const __half* __restrict__ A, const __half* __restrict__ B,
            const float* __restrict__ bias, float* __restrict__ C, int N,
            const float* __restrict__ qn_w, const float* __restrict__ kn_w)
{
    extern __shared__ char ts[];
    const int tid = threadIdx.x;
    const int K = 3072, nk = 48;
    const int n0 = blockIdx.y * 256;

#if defined(TC_ON)
    // ---------------- tcgen05 cg2 path ----------------
    const uint32_t sb = smaddr(ts);
    const uint32_t ab = (sb + 2048 + 1023) & ~1023u;
    const uint32_t tmem_ptr_addr = sb;
    const uint32_t mbd0 = sb + 8;    // done mbars  [4] x 8B (multicast target)
    const uint32_t mbr0 = sb + 40;   // ready mbars [4] x 8B (rank0's used)
    float* wsm = (float*)ts + 64;    // byte 256..1280: [0:128)=qn, [128:256)=kn
    const uint32_t rank = ctarank();
    const int m0 = blockIdx.z * 256 + (int)rank * 128;   // own A/D rows

    if (tid < 32)
        asm volatile("tcgen05.alloc.cta_group::2.sync.aligned.shared::cta.b32 [%0], %1;"
                     :: "r"(tmem_ptr_addr), "r"(256u) : "memory");
    if (tid == 0)
        for (int i = 0; i < 4; ++i) {
            mbar_init(mbd0 + 8 * i, 1);
            mbar_init(mbr0 + 8 * i, 2);
        }
    if (MODE == 1) {
        if (tid < 128) wsm[tid] = qn_w[tid];
        else           wsm[tid] = kn_w[tid - 128];
    }
    __syncthreads();
    CLUSTER_ARRIVE(); CLUSTER_WAIT();   // mbars + TMEM alloc visible pair-wide

    uint32_t tmem;
    asm volatile("ld.shared.b32 %0,[%1];" : "=r"(tmem) : "r"(tmem_ptr_addr));

    const __half* Agb = A + (size_t)m0 * K;                    // own A rows
    const __half* Bgb = B + (size_t)(n0 + rank * 128) * K;     // own B rows

    auto fill = [&](int s, int kc) {
        uint32_t base = ab + s * TSTAGE;
        const __half* Agp = Agb + kc * 64;
        const __half* Bgp = Bgb + kc * 64;
        #pragma unroll
        for (int it = 0; it < 4; ++it) {            // A: 128 rows x 8 x 16B
            int idx = it * 256 + tid;
            int r = idx >> 3, ch = idx & 7;
            cpa16(base + SMEM_SWIZZLE_128B(r * 128 + ch * 16),
                  Agp + (size_t)r * K + ch * 8);
        }
        #pragma unroll
        for (int it = 0; it < 4; ++it) {            // B: 128 rows x 8 x 16B
            int idx = it * 256 + tid;
            int r = idx >> 3, ch = idx & 7;
            cpa16(base + TAB + SMEM_SWIZZLE_128B(r * 128 + ch * 16),
                  Bgp + (size_t)r * K + ch * 8);
        }
        CP_COMMIT();
    };

    fill(0, 0); fill(1, 1); fill(2, 2);

    // idesc: F32 acc, f16 x f16, N=256, M_TOTAL=256 (cg2)
    const uint32_t idesc = (1u << 4) | (32u << 17) | (16u << 24);
    int phd[4] = {0, 0, 0, 0};
    int phr[4] = {0, 0, 0, 0};

    for (int ks = 0; ks < nk; ++ks) {
        const int s = ks & 3;
        CP_WAIT(2);                 // own chunk ks resident
        __syncthreads();

        if (tid == 0) {
            asm volatile("fence.proxy.async.shared::cta;" ::: "memory");
            if (rank == 0) mbar_arrive_local(mbr0 + 8 * s);
            else           mbar_arrive_cluster_rank(mbr0 + 8 * s, 0);
        }
        if (rank == 0 && tid == 0) {
            mbar_wait(mbr0 + 8 * s, phr[s]);   // both CTAs' chunk ks ready
            phr[s] ^= 1;
            uint32_t base = ab + s * TSTAGE;
            uint64_t ad = mk_desc(base);
            uint64_t bd = mk_desc(base + TAB);
            #pragma unroll
            for (int sub = 0; sub < 4; ++sub)
                mma_f16_ss_cg2(tmem, ad + sub * 2, bd + sub * 2, idesc,
                               (ks > 0) || (sub > 0));
            tc_commit_mc2(mbd0 + 8 * s);       // arrives in BOTH CTAs
        }

        if (ks + 3 < nk) {
            const int nxt = (ks + 3) & 3;
            if (ks >= 1) {
                mbar_wait(mbd0 + 8 * nxt, phd[nxt]);
                phd[nxt] ^= 1;
            }
            fill(nxt, ks + 3);
        } else {
            CP_COMMIT();            // keep one-group-per-iter ledger
        }
    }

    {   // final: wait for last MMA batch (multicast done in both CTAs)
        const int sl = (nk - 1) & 3;
        mbar_wait(mbd0 + 8 * sl, phd[sl]);
    }
    asm volatile("tcgen05.fence::after_thread_sync;" ::: "memory");
    __syncthreads();

    // Epilogue: warps 0-3 read this CTA's 128 D rows x 256 cols.
    const int w = tid >> 5, lane = tid & 31;
    if (w < 4) {
        const int row = m0 + w * 32 + lane;
        if (MODE == 0) {
            #pragma unroll
            for (int chunk = 0; chunk < 8; ++chunk) {
                uint32_t dr[32];
                LDTM_X32(dr, tmem + chunk * 32);
                asm volatile("tcgen05.wait::ld.sync.aligned;" ::: "memory");
                const int col0 = n0 + chunk * 32;
                float* Crow = C + (size_t)row * N + col0;
                #pragma unroll
                for (int j = 0; j < 32; j += 4) {
                    float4 v = make_float4(__uint_as_float(dr[j])   + bias[col0 + j],
                                           __uint_as_float(dr[j+1]) + bias[col0 + j + 1],
                                           __uint_as_float(dr[j+2]) + bias[col0 + j + 2],
                                           __uint_as_float(dr[j+3]) + bias[col0 + j + 3]);
                    *(float4*)(Crow + j) = v;
                }
            }
        } else {
            const int part = n0 / CM;
            const int head0 = (n0 % CM) >> 7;
            const int b = row >> 11, tok = row & (NTOK - 1);
            if (part == 2) {
                #pragma unroll
                for (int chunk = 0; chunk < 8; ++chunk) {
                    uint32_t dr[32];
                    LDTM_X32(dr, tmem + chunk * 32);
                    asm volatile("tcgen05.wait::ld.sync.aligned;" ::: "memory");
                    const int col0 = n0 + chunk * 32;
                    const int head = head0 + (chunk >> 2), d0 = (chunk & 3) * 32;
                    __half* dst = g_v16 +
                        (((size_t)b * HEADS + head) * NTOK + tok) * DHEAD + d0;
                    #pragma unroll
                    for (int j = 0; j < 32; j += 2)
                        *(__half2*)(dst + j) = __floats2half2_rn(
                            __uint_as_float(dr[j])   + bias[col0 + j],
                            __uint_as_float(dr[j+1]) + bias[col0 + j + 1]);
                }
            } else {
                const float* ws = (part == 0) ? wsm : wsm + 128;
                const float sc = (part == 0) ? 0.08838834764831845f : 1.0f;
                __half* dstb = (part == 0) ? g_q16 : g_k16;
                #pragma unroll
                for (int hh = 0; hh < 2; ++hh) {
                    float x[128];
                    #pragma unroll
                    for (int c4 = 0; c4 < 4; ++c4) {
                        uint32_t* xr = (uint32_t*)&x[c4 * 32];
                        LDTM_X32(xr, tmem + (hh * 4 + c4) * 32);
                        asm volatile("tcgen05.wait::ld.sync.aligned;" ::: "memory");
                        const int col0 = n0 + (hh * 4 + c4) * 32;
                        #pragma unroll
                        for (int j = 0; j < 32; ++j)
                            x[c4 * 32 + j] = __uint_as_float(xr[j]) + bias[col0 + j];
                    }
                    float ss = 0.f;
                    #pragma unroll
                    for (int j = 0; j < 128; ++j) ss += x[j] * x[j];
                    const float rn = rsqrtf(ss * (1.f / DHEAD) + 1e-6f);
                    __half* dst = dstb +
                        (((size_t)b * HEADS + head0 + hh) * NTOK + tok) * DHEAD;
                    const float2* rt = g_rtab + (size_t)tok * 64;
                    #pragma unroll
                    for (int p = 0; p < 64; ++p) {
                        float2 t = rt[p];
                        float y0 = x[2*p]     * rn * ws[2*p];
                        float y1 = x[2*p + 1] * rn * ws[2*p + 1];
                        float o0 = (y0 * t.x - y1 * t.y) * sc;
                        float o1 = (y1 * t.x + y0 * t.y) * sc;
                        *(__half2*)(dst + 2*p) = __floats2half2_rn(o0, o1);
                    }
                }
            }
        }
    }
    __syncthreads();
    CLUSTER_ARRIVE(); CLUSTER_WAIT();   // pair's MMA/TMEM must be fully done
    if (tid < 32) {
        asm volatile("tcgen05.relinquish_alloc_permit.cta_group::2.sync.aligned;");
        asm volatile("tcgen05.dealloc.cta_group::2.sync.aligned.b32 %0, %1;"
                     :: "r"(tmem), "r"(256u));
    }

#else
    // -------- mma.sync fallback (compile-validity on non-'a' passes only) ---
    __half* sh = (__half*)ts;
    const int m0 = blockIdx.z * 256 + blockIdx.x * 128;
    const int lane = tid & 31, warp = tid >> 5;
    const int g = lane >> 2, cq = lane & 3;
    const int wm = warp >> 2, wn = warp & 3;
    const int GST = 128 * 40, GSTG = 2 * GST;

    for (int half = 0; half < 2; ++half) {
        const int nh0 = n0 + half * 128;
        const int lrow = tid >> 2, lch = tid & 3;
        const __half* Ag = A + (size_t)(m0 + lrow) * K + lch * 8;
        const __half* Bg = B + (size_t)(nh0 + lrow) * K + lch * 8;

        float acc[4][4][4] = {};

        auto issue = [&](int s, int k0) {
            __half* As = sh + s * GSTG;
            __half* Bs = As + GST;
            uint32_t da = smaddr(As + lrow * 40 + lch * 8);
            uint32_t db = smaddr(Bs + lrow * 40 + lch * 8);
            cpa16(da,            Ag + k0);
            cpa16(da + 64*40*2,  Ag + (size_t)64 * K + k0);
            cpa16(db,            Bg + k0);
            cpa16(db + 64*40*2,  Bg + (size_t)64 * K + k0);
        };

        issue(0, 0);  CP_COMMIT();
        issue(1, 32); CP_COMMIT();
        issue(2, 64); CP_COMMIT();

        const int nk32 = K / 32;
        for (int ks = 0; ks < nk32; ++ks) {
            if (ks == nk32 - 1) { CP_WAIT(0); } else { CP_WAIT(1); }
            __syncthreads();
            if (ks + 3 < nk32) issue((ks + 3) & 3, (ks + 3) * 32);
            CP_COMMIT();

            const __half* As = sh + (ks & 3) * GSTG;
            const __half* Bs = As + GST;
            #pragma unroll
            for (int kk = 0; kk < 2; ++kk) {
                uint32_t af[4][4], bf[4][2];
                #pragma unroll
                for (int mt = 0; mt < 4; ++mt)
                    ldsm4(af[mt][0], af[mt][1], af[mt][2], af[mt][3],
                          smaddr(As + (wm*64 + mt*16 + (lane & 15)) * 40
                                    + kk*16 + (lane >> 4) * 8));
                #pragma unroll
                for (int p = 0; p < 2; ++p)
                    ldsm4(bf[2*p][0], bf[2*p+1][0], bf[2*p][1], bf[2*p+1][1],
                          smaddr(Bs + (wn*32 + p*16 + (lane & 15)) * 40
                                    + kk*16 + (lane >> 4) * 8));
                #pragma unroll
                for (int mt = 0; mt < 4; ++mt)
                    #pragma unroll
                    for (int nt = 0; nt < 4; ++nt)
                        mma16(acc[mt][nt], af[mt], bf[nt]);
            }
            __syncthreads();
        }

        #pragma unroll
        for (int mt = 0; mt < 4; ++mt) {
            int r0 = m0 + wm*64 + mt*16 + g;
            int r1 = r0 + 8;
            #pragma unroll
            for (int nt = 0; nt < 4; ++nt) {
                int col = nh0 + wn*32 + nt*8 + 2*cq;
                float b0 = bias[col], b1 = bias[col + 1];
                float2 v0 = make_float2(acc[mt][nt][0] + b0, acc[mt][nt][1] + b1);
                float2 v1 = make_float2(acc[mt][nt][2] + b0, acc[mt][nt][3] + b1);
                if (MODE == 0) {
                    *(float2*)(C + (size_t)r0 * N + col) = v0;
                    *(float2*)(C + (size_t)r1 * N + col) = v1;
                } else {
                    int part = col / CM;
                    int within = col % CM;
                    int head = within >> 7;
                    int d = within & 127;
                    int b0i = r0 >> 11, t0 = r0 & (NTOK - 1);
                    int b1i = r1 >> 11, t1 = r1 & (NTOK - 1);
                    size_t o0 = (((size_t)b0i * HEADS + head) * NTOK + t0) * DHEAD + d;
                    size_t o1 = (((size_t)b1i * HEADS + head) * NTOK + t1) * DHEAD + d;
                    if (part == 0) {
                        *(float2*)(g_q + o0) = v0; *(float2*)(g_q + o1) = v1;
                    } else if (part == 1) {
                        *(float2*)(g_k + o0) = v0; *(float2*)(g_k + o1) = v1;
                    } else {
                        *(__half2*)(g_v16 + o0) = __floats2half2_rn(v0.x, v0.y);
                        *(__half2*)(g_v16 + o1) = __floats2half2_rn(v1.x, v1.y);
                    }
                }
            }
        }
        __syncthreads();
    }
#endif
}

// ---------------------------------------------------------------------------
// Flash attention, fp16 mma.sync. Br=128 (8 warps x 16 rows), Bc=64.
// (unchanged from round 9 — proven)
// ---------------------------------------------------------------------------
#define FKV 8704                // 64*136 halves
#define FSTG (2 * FKV)

__global__ __launch_bounds__(256, 1)
void flash_h()
{
    extern __shared__ __half fsh[];

    const int tid = threadIdx.x, lane = tid & 31, w = tid >> 5;
    const int g = lane >> 2, cq = lane & 3;
    const int q0 = blockIdx.x * 128;
    const size_t hb = ((size_t)blockIdx.z * HEADS + blockIdx.y) * NTOK * DHEAD;
    const __half* Qg = g_q16 + hb + (size_t)q0 * DHEAD;
    const __half* Kg = g_k16 + hb;
    const __half* Vg = g_v16 + hb;

    {
        #pragma unroll
        for (int it = 0; it < 8; ++it) {
            int cid = it * 256 + tid;
            int r = cid >> 4, ch = cid & 15;
            *(uint4*)(fsh + r * 136 + ch * 8) = *(const uint4*)(Qg + r * 128 + ch * 8);
        }
    }
    __syncthreads();
    uint32_t qa[8][4];
    #pragma unroll
    for (int kk = 0; kk < 8; ++kk)
        ldsm4(qa[kk][0], qa[kk][1], qa[kk][2], qa[kk][3],
              smaddr(fsh + (w*16 + (lane & 15)) * 136 + kk*16 + (lane >> 4) * 8));
    __syncthreads();

    auto issueKV = [&](int s, int c0) {
        __half* Kst = fsh + s * FSTG;
        __half* Vst = Kst + FKV;
        const __half* Kp = Kg + (size_t)c0 * DHEAD;
        const __half* Vp = Vg + (size_t)c0 * DHEAD;
        #pragma unroll
        for (int it = 0; it < 4; ++it) {
            int cid = it * 256 + tid;
            int r = cid >> 4, ch = cid & 15;
            cpa16(smaddr(Kst + r * 136 + ch * 8), Kp + r * 128 + ch * 8);
            cpa16(smaddr(Vst + r * 136 + ch * 8), Vp + r * 128 + ch * 8);
        }
    };

    float od[16][4] = {};
    float m0 = -INFINITY, m1 = -INFINITY, l0 = 0.f, l1 = 0.f;

    issueKV(0, 0); CP_COMMIT();

    for (int c = 0; c < NTOK / 64; ++c) {
        if (c + 1 < NTOK / 64) issueKV((c + 1) & 1, (c + 1) * 64);
        CP_COMMIT();
        CP_WAIT(1);
        __syncthreads();

        const __half* Kst = fsh + (c & 1) * FSTG;
        const __half* Vst = Kst + FKV;

        float s[8][4] = {};
        #pragma unroll
        for (int kk = 0; kk < 8; ++kk) {
            uint32_t bf[8][2];
            #pragma unroll
            for (int p = 0; p < 4; ++p)
                ldsm4(bf[2*p][0], bf[2*p+1][0], bf[2*p][1], bf[2*p+1][1],
                      smaddr(Kst + (p*16 + (lane & 15)) * 136
                                 + kk*16 + (lane >> 4) * 8));
            #pragma unroll
            for (int nt = 0; nt < 8; ++nt)
                mma16(s[nt], qa[kk], bf[nt]);
        }

        float cm0 = -INFINITY, cm1 = -INFINITY;
        #pragma unroll
        for (int nt = 0; nt < 8; ++nt) {
            cm0 = fmaxf(cm0, fmaxf(s[nt][0], s[nt][1]));
            cm1 = fmaxf(cm1, fmaxf(s[nt][2], s[nt][3]));
        }
        cm0 = fmaxf(cm0, __shfl_xor_sync(0xffffffffu, cm0, 1));
        cm0 = fmaxf(cm0, __shfl_xor_sync(0xffffffffu, cm0, 2));
        cm1 = fmaxf(cm1, __shfl_xor_sync(0xffffffffu, cm1, 1));
        cm1 = fmaxf(cm1, __shfl_xor_sync(0xffffffffu, cm1, 2));
        float mn0 = fmaxf(m0, cm0), mn1 = fmaxf(m1, cm1);
        float al0 = __expf(m0 - mn0), al1 = __expf(m1 - mn1);
        m0 = mn0; m1 = mn1;

        float rs0 = 0.f, rs1 = 0.f;
        #pragma unroll
        for (int nt = 0; nt < 8; ++nt) {
            s[nt][0] = __expf(s[nt][0] - mn0); rs0 += s[nt][0];
            s[nt][1] = __expf(s[nt][1] - mn0); rs0 += s[nt][1];
            s[nt][2] = __expf(s[nt][2] - mn1); rs1 += s[nt][2];
            s[nt][3] = __expf(s[nt][3] - mn1); rs1 += s[nt][3];
        }
        rs0 += __shfl_xor_sync(0xffffffffu, rs0, 1);
        rs0 += __shfl_xor_sync(0xffffffffu, rs0, 2);
        rs1 += __shfl_xor_sync(0xffffffffu, rs1, 1);
        rs1 += __shfl_xor_sync(0xffffffffu, rs1, 2);
        l0 = l0 * al0 + rs0;
        l1 = l1 * al1 + rs1;

        #pragma unroll
        for (int dt = 0; dt < 16; ++dt) {
            od[dt][0] *= al0; od[dt][1] *= al0;
            od[dt][2] *= al1; od[dt][3] *= al1;
        }

        uint32_t pa[4][4];
        #pragma unroll
        for (int k2 = 0; k2 < 4; ++k2) {
            pa[k2][0] = h2u(s[2*k2][0],   s[2*k2][1]);
            pa[k2][1] = h2u(s[2*k2][2],   s[2*k2][3]);
            pa[k2][2] = h2u(s[2*k2+1][0], s[2*k2+1][1]);
            pa[k2][3] = h2u(s[2*k2+1][2], s[2*k2+1][3]);
        }

        #pragma unroll
        for (int k2 = 0; k2 < 4; ++k2) {
            #pragma unroll
            for (int dp = 0; dp < 8; ++dp) {
                uint32_t v0, v1, v2, v3;
                int t = lane >> 3, r = lane & 7;
                ldsm4t(v0, v1, v2, v3,
                       smaddr(Vst + (k2*16 + (t & 1)*8 + r) * 136
                                  + dp*16 + (t >> 1)*8));
                uint32_t b0[2] = {v0, v1}, b1[2] = {v2, v3};
                mma16(od[2*dp],     pa[k2], b0);
                mma16(od[2*dp + 1], pa[k2], b1);
            }
        }
        __syncthreads();
    }

    float inv0 = 1.f / l0, inv1 = 1.f / l1;
    int r0 = q0 + w*16 + g, r1 = r0 + 8;
    size_t base0 = (((size_t)blockIdx.z * NTOK + r0) * HEADS + blockIdx.y) * DHEAD;
    size_t base1 = (((size_t)blockIdx.z * NTOK + r1) * HEADS + blockIdx.y) * DHEAD;
    #pragma unroll
    for (int dt = 0; dt < 16; ++dt) {
        int col = dt*8 + 2*cq;
        *(__half2*)(g_att16 + base0 + col) =
            __floats2half2_rn(od[dt][0] * inv0, od[dt][1] * inv0);
        *(__half2*)(g_att16 + base1 + col) =
            __floats2half2_rn(od[dt][2] * inv1, od[dt][3] * inv1);
    }
}

// ---------------------------------------------------------------------------
extern "C" void kernel_launch(void* const* d_in, const int* in_sizes, int n_in,
                              void* d_out, int out_size)
{
    const float* x      = (const float*)d_in[0];
    const float* qkv_w  = (const float*)d_in[1];
    const float* qkv_b  = (const float*)d_in[2];
    const float* qn_w   = (const float*)d_in[3];
    const float* kn_w   = (const float*)d_in[4];
    const float* proj_w = (const float*)d_in[5];
    const float* proj_b = (const float*)d_in[6];
    float* out = (float*)d_out;

    __half *x16, *w16, *pw16, *att16;
    cudaGetSymbolAddress((void**)&x16,   g_x16);
    cudaGetSymbolAddress((void**)&w16,   g_w16);
    cudaGetSymbolAddress((void**)&pw16,  g_pw16);
    cudaGetSymbolAddress((void**)&att16, g_att16);

    // 0) fp32 -> fp16 pre-conversion + RoPE cos/sin table
    f2h_kernel<<<1024, 256>>>((const float4*)x,      (uint4*)x16,  MTOT * CM / 8);
    f2h_kernel<<<2048, 256>>>((const float4*)qkv_w,  (uint4*)w16,  3 * CM * CM / 8);
    f2h_kernel<<<1024, 256>>>((const float4*)proj_w, (uint4*)pw16, CM * CM / 8);
    rope_tab_kernel<<<NTOK, 64>>>();

    cudaFuncSetAttribute(gemm_u<1>, cudaFuncAttributeMaxDynamicSharedMemorySize, GEMM_SMEM);
    cudaFuncSetAttribute(gemm_u<0>, cudaFuncAttributeMaxDynamicSharedMemorySize, GEMM_SMEM);
    const int fsm = 2 * FSTG * (int)sizeof(__half);     // 69632 B
    cudaFuncSetAttribute(flash_h, cudaFuncAttributeMaxDynamicSharedMemorySize, fsm);

    // 1) QKV GEMM (cg2, cluster on X) -> q16/k16/v16 with fused rope/rms
    gemm_u<1><<<dim3(2, 3 * CM / 256, MTOT / 256), 256, GEMM_SMEM>>>(
        x16, w16, qkv_b, nullptr, 3 * CM, qn_w, kn_w);

    // 2) Flash attention -> fp16 att [B,N,H,D]
    flash_h<<<dim3(NTOK / 128, HEADS, BATCH), 256, fsm>>>();

    // 3) Output projection (cg2) -> fp32 out
    gemm_u<0><<<dim3(2, CM / 256, MTOT / 256), 256, GEMM_SMEM>>>(
        att16, pw16, proj_b, out, CM, nullptr, nullptr);
}

// round 13
// speedup vs baseline: 1.0234x; 1.0234x over previous
#include <cuda_runtime.h>
#include <cuda_fp16.h>
#include <math.h>
#include <stdint.h>

#define BATCH 2
#define NTOK  2048
#define HEADS 24
#define DHEAD 128
#define CM    3072
#define MTOT  (BATCH*NTOK)   // 4096

// fp32 scratch — used only by the non-'a' fallback path.
__device__ __align__(256) float g_q[(size_t)BATCH*HEADS*NTOK*DHEAD];
__device__ __align__(256) float g_k[(size_t)BATCH*HEADS*NTOK*DHEAD];
// fp16 scratch
__device__ __align__(256) __half g_x16[(size_t)MTOT*CM];
__device__ __align__(256) __half g_w16[(size_t)3*CM*CM];
__device__ __align__(256) __half g_pw16[(size_t)CM*CM];
__device__ __align__(256) __half g_q16[(size_t)BATCH*HEADS*NTOK*DHEAD];
__device__ __align__(256) __half g_k16[(size_t)BATCH*HEADS*NTOK*DHEAD];
__device__ __align__(256) __half g_v16[(size_t)BATCH*HEADS*NTOK*DHEAD];
__device__ __align__(256) __half g_att16[(size_t)MTOT*CM];
// RoPE cos/sin table: [tok][pair]
__device__ __align__(256) float2 g_rtab[(size_t)NTOK*64];

// ---------------------------------------------------------------------------
// base-ISA helpers
// ---------------------------------------------------------------------------
__device__ __forceinline__ uint32_t smaddr(const void* p) {
    return (uint32_t)__cvta_generic_to_shared(p);
}
__device__ __forceinline__ void ldsm4(uint32_t& r0, uint32_t& r1, uint32_t& r2,
                                      uint32_t& r3, uint32_t a) {
    asm volatile("ldmatrix.sync.aligned.m8n8.x4.shared.b16 {%0,%1,%2,%3},[%4];"
                 : "=r"(r0), "=r"(r1), "=r"(r2), "=r"(r3) : "r"(a));
}
__device__ __forceinline__ void ldsm4t(uint32_t& r0, uint32_t& r1, uint32_t& r2,
                                       uint32_t& r3, uint32_t a) {
    asm volatile("ldmatrix.sync.aligned.m8n8.x4.trans.shared.b16 {%0,%1,%2,%3},[%4];"
                 : "=r"(r0), "=r"(r1), "=r"(r2), "=r"(r3) : "r"(a));
}
__device__ __forceinline__ void mma16(float c[4], const uint32_t a[4], const uint32_t b[2]) {
    asm volatile("mma.sync.aligned.m16n8k16.row.col.f32.f16.f16.f32 "
                 "{%0,%1,%2,%3},{%4,%5,%6,%7},{%8,%9},{%0,%1,%2,%3};"
                 : "+f"(c[0]), "+f"(c[1]), "+f"(c[2]), "+f"(c[3])
                 : "r"(a[0]), "r"(a[1]), "r"(a[2]), "r"(a[3]), "r"(b[0]), "r"(b[1]));
}
__device__ __forceinline__ void cpa16(uint32_t s, const void* g) {
    asm volatile("cp.async.cg.shared.global [%0],[%1],16;" :: "r"(s), "l"(g));
}
#define CP_COMMIT() asm volatile("cp.async.commit_group;")
#define CP_WAIT(n)  asm volatile("cp.async.wait_group %0;" :: "n"(n))
__device__ __forceinline__ uint32_t h2u(float lo, float hi) {
    __half2 h = __floats2half2_rn(lo, hi);
    return *(uint32_t*)&h;
}
__device__ __forceinline__ void mbar_init(uint32_t a, uint32_t c) {
    asm volatile("mbarrier.init.shared.b64 [%0], %1;" :: "r"(a), "r"(c) : "memory");
}
__device__ __forceinline__ void mbar_wait(uint32_t mbar, uint32_t parity) {
    asm volatile("{\n\t.reg .pred P1;\n\t"
                 "W_%=:\n\t"
                 "mbarrier.try_wait.parity.acquire.cta.shared::cta.b64 P1, [%0], %1, 0x989680;\n\t"
                 "@P1 bra.uni D_%=;\n\t"
                 "bra.uni W_%=;\n\t"
                 "D_%=:\n\t}" :: "r"(mbar), "r"(parity) : "memory");
}

#define SMEM_SWIZZLE_128B(o) ((o) ^ (((o) >> 3) & 0x70))

// ---------------------------------------------------------------------------
// tcgen05 helpers — sm_103a ('a' feature) pass only.
// ---------------------------------------------------------------------------
#if defined(__CUDA_ARCH_FEAT_SM103_ALL) || defined(__CUDA_ARCH_FEAT_SM100_ALL)
#define TC_ON 1
static constexpr uint64_t SMEM_DESC_BASE_SW128 =
    (uint64_t(2)  << 61) | (uint64_t(1) << 46) | (uint64_t(64) << 32) | (uint64_t(1) << 16);
__device__ __forceinline__ uint64_t mk_desc(uint32_t a) {
    return SMEM_DESC_BASE_SW128 | ((uint64_t)(a >> 4) & 0x3FFF);
}
__device__ __forceinline__ void mma_f16_ss_cg1(uint32_t d, uint64_t ad, uint64_t bd,
                                               uint32_t idesc, bool acc) {
    uint32_t en = acc ? 1u : 0u;
    asm volatile("{\n\t.reg .pred p;\n\tsetp.ne.u32 p, %4, 0;\n\t"
                 "tcgen05.mma.cta_group::1.kind::f16 [%0], %1, %2, %3, {%5,%5,%5,%5}, p;\n\t}"
                 :: "r"(d), "l"(ad), "l"(bd), "r"(idesc), "r"(en), "r"(0u) : "memory");
}
__device__ __forceinline__ void tc_commit(uint32_t mbar) {
    asm volatile("tcgen05.commit.cta_group::1.mbarrier::arrive::one.shared::cluster.b64 [%0];"
                 :: "r"(mbar) : "memory");
}
#define LDTM_X32(r, addr) \
    asm volatile("tcgen05.ld.sync.aligned.32x32b.x32.b32 " \
        "{%0,%1,%2,%3,%4,%5,%6,%7,%8,%9,%10,%11,%12,%13,%14,%15," \
        "%16,%17,%18,%19,%20,%21,%22,%23,%24,%25,%26,%27,%28,%29,%30,%31},[%32];" \
        : "=r"((r)[0]),"=r"((r)[1]),"=r"((r)[2]),"=r"((r)[3]), \
          "=r"((r)[4]),"=r"((r)[5]),"=r"((r)[6]),"=r"((r)[7]), \
          "=r"((r)[8]),"=r"((r)[9]),"=r"((r)[10]),"=r"((r)[11]), \
          "=r"((r)[12]),"=r"((r)[13]),"=r"((r)[14]),"=r"((r)[15]), \
          "=r"((r)[16]),"=r"((r)[17]),"=r"((r)[18]),"=r"((r)[19]), \
          "=r"((r)[20]),"=r"((r)[21]),"=r"((r)[22]),"=r"((r)[23]), \
          "=r"((r)[24]),"=r"((r)[25]),"=r"((r)[26]),"=r"((r)[27]), \
          "=r"((r)[28]),"=r"((r)[29]),"=r"((r)[30]),"=r"((r)[31]) \
        : "r"(addr))
#endif

// ---------------------------------------------------------------------------
// fp32 -> fp16 converter
// ---------------------------------------------------------------------------
__global__ void f2h_kernel(const float4* __restrict__ src, uint4* __restrict__ dst,
                           int n8)
{
    for (int i = blockIdx.x * blockDim.x + threadIdx.x; i < n8;
         i += gridDim.x * blockDim.x) {
        float4 a = src[2 * i], b = src[2 * i + 1];
        dst[i] = make_uint4(h2u(a.x, a.y), h2u(a.z, a.w), h2u(b.x, b.y), h2u(b.z, b.w));
    }
}

// ---------------------------------------------------------------------------
// RoPE table
// ---------------------------------------------------------------------------
__global__ void rope_tab_kernel()
{
    int idx = blockIdx.x * 64 + threadIdx.x;
    int tok = idx >> 6, p = idx & 63;
    int d = 2 * p;
    float pos, e;
    if (d < 44)      { pos = (float)(tok >> 8);        e = (float)d        * (1.f / 44.f); }
    else if (d < 86) { pos = (float)((tok >> 4) & 15); e = (float)(d - 44) * (1.f / 42.f); }
    else             { pos = (float)(tok & 15);        e = (float)(d - 86) * (1.f / 42.f); }
    float f = expf(-9.210340371976184f * e);
    float cs, sn;
    sincosf(pos * f, &sn, &cs);
    g_rtab[idx] = make_float2(cs, sn);
}

// ---------------------------------------------------------------------------
// Unified GEMM-NT (cg1, round-9 proven): C = A·B^T + bias, K = 3072.
// Grid (N/256, M/128), 256 threads. tcgen05 f16 SS, BM=128 BN=256 BK=64,
// 4-stage cp.async, one commit group per iter; CP_WAIT(2) retires chunk ks.
// MODE 0: fp32 C. MODE 1: QKV epilogue with fused rope/rms (q,k), bias (v).
// ---------------------------------------------------------------------------
#define TSTAGE  49152            // A 16KB + B 32KB per stage
#define TAB     16384
#define GEMM_SMEM (3072 + 4 * TSTAGE)

template<int MODE>
__global__ __launch_bounds__(256, 1)
void gemm_u(const __half* __restrict__ A, const __half* __restrict__ B,
            const float* __restrict__ bias, float* __restrict__ C, int N,
            const float* __restrict__ qn_w, const float* __restrict__ kn_w)
{
    extern __shared__ char ts[];
    const int tid = threadIdx.x;
    const int K = 3072, nk = 48;
    const int n0 = blockIdx.x * 256, m0 = blockIdx.y * 128;

#if defined(TC_ON)
    const uint32_t sb = smaddr(ts);
    const uint32_t ab = (sb + 2048 + 1023) & ~1023u;
    const uint32_t tmem_ptr_addr = sb;
    const uint32_t mbs0 = sb + 8;
    float* wsm = (float*)ts + 64;

    if (tid < 32)
        asm volatile("tcgen05.alloc.cta_group::1.sync.aligned.shared::cta.b32 [%0], %1;"
                     :: "r"(tmem_ptr_addr), "r"(256u) : "memory");
    if (tid == 0)
        for (int i = 0; i < 4; ++i) mbar_init(mbs0 + 8 * i, 1);
    if (MODE == 1) {
        if (tid < 128) wsm[tid] = qn_w[tid];
        else           wsm[tid] = kn_w[tid - 128];
    }
    __syncthreads();
    uint32_t tmem;
    asm volatile("ld.shared.b32 %0,[%1];" : "=r"(tmem) : "r"(tmem_ptr_addr));

    const __half* Agb = A + (size_t)m0 * K;
    const __half* Bgb = B + (size_t)n0 * K;

    auto fill = [&](int s, int kc) {
        uint32_t base = ab + s * TSTAGE;
        const __half* Agp = Agb + kc * 64;
        const __half* Bgp = Bgb + kc * 64;
        #pragma unroll
        for (int it = 0; it < 4; ++it) {
            int idx = it * 256 + tid;
            int r = idx >> 3, ch = idx & 7;
            cpa16(base + SMEM_SWIZZLE_128B(r * 128 + ch * 16),
                  Agp + (size_t)r * K + ch * 8);
        }
        #pragma unroll
        for (int it = 0; it < 8; ++it) {
            int idx = it * 256 + tid;
            int r = idx >> 3, ch = idx & 7;
            cpa16(base + TAB + SMEM_SWIZZLE_128B(r * 128 + ch * 16),
                  Bgp + (size_t)r * K + ch * 8);
        }
        CP_COMMIT();
    };

    fill(0, 0); fill(1, 1); fill(2, 2);

    const uint32_t idesc = (1u << 4) | (32u << 17) | (8u << 24);
    int ph[4] = {0, 0, 0, 0};

    for (int ks = 0; ks < nk; ++ks) {
        const int s = ks & 3;
        CP_WAIT(2);
        __syncthreads();

        if (tid == 0) {
            asm volatile("fence.proxy.async.shared::cta;" ::: "memory");
            uint32_t base = ab + s * TSTAGE;
            uint64_t ad = mk_desc(base);
            uint64_t bd = mk_desc(base + TAB);
            #pragma unroll
            for (int sub = 0; sub < 4; ++sub)
                mma_f16_ss_cg1(tmem, ad + sub * 2, bd + sub * 2, idesc,
                               (ks > 0) || (sub > 0));
            tc_commit(mbs0 + 8 * s);
        }

        if (ks + 3 < nk) {
            const int nxt = (ks + 3) & 3;
            if (ks >= 1) {
                mbar_wait(mbs0 + 8 * nxt, ph[nxt]);
                ph[nxt] ^= 1;
            }
            fill(nxt, ks + 3);
        } else {
            CP_COMMIT();
        }
    }

    {
        const int sl = (nk - 1) & 3;
        mbar_wait(mbs0 + 8 * sl, ph[sl]);
    }
    asm volatile("tcgen05.fence::after_thread_sync;" ::: "memory");
    __syncthreads();

    const int w = tid >> 5, lane = tid & 31;
    if (w < 4) {
        const int row = m0 + w * 32 + lane;
        if (MODE == 0) {
            #pragma unroll
            for (int chunk = 0; chunk < 8; ++chunk) {
                uint32_t dr[32];
                LDTM_X32(dr, tmem + chunk * 32);
                asm volatile("tcgen05.wait::ld.sync.aligned;" ::: "memory");
                const int col0 = n0 + chunk * 32;
                float* Crow = C + (size_t)row * N + col0;
                #pragma unroll
                for (int j = 0; j < 32; j += 4) {
                    float4 v = make_float4(__uint_as_float(dr[j])   + bias[col0 + j],
                                           __uint_as_float(dr[j+1]) + bias[col0 + j + 1],
                                           __uint_as_float(dr[j+2]) + bias[col0 + j + 2],
                                           __uint_as_float(dr[j+3]) + bias[col0 + j + 3]);
                    *(float4*)(Crow + j) = v;
                }
            }
        } else {
            const int part = n0 / CM;
            const int head0 = (n0 % CM) >> 7;
            const int b = row >> 11, tok = row & (NTOK - 1);
            if (part == 2) {
                #pragma unroll
                for (int chunk = 0; chunk < 8; ++chunk) {
                    uint32_t dr[32];
                    LDTM_X32(dr, tmem + chunk * 32);
                    asm volatile("tcgen05.wait::ld.sync.aligned;" ::: "memory");
                    const int col0 = n0 + chunk * 32;
                    const int head = head0 + (chunk >> 2), d0 = (chunk & 3) * 32;
                    __half* dst = g_v16 +
                        (((size_t)b * HEADS + head) * NTOK + tok) * DHEAD + d0;
                    #pragma unroll
                    for (int j = 0; j < 32; j += 2)
                        *(__half2*)(dst + j) = __floats2half2_rn(
                            __uint_as_float(dr[j])   + bias[col0 + j],
                            __uint_as_float(dr[j+1]) + bias[col0 + j + 1]);
                }
            } else {
                const float* ws = (part == 0) ? wsm : wsm + 128;
                const float sc = (part == 0) ? 0.08838834764831845f : 1.0f;
                __half* dstb = (part == 0) ? g_q16 : g_k16;
                #pragma unroll
                for (int hh = 0; hh < 2; ++hh) {
                    float x[128];
                    #pragma unroll
                    for (int c4 = 0; c4 < 4; ++c4) {
                        uint32_t* xr = (uint32_t*)&x[c4 * 32];
                        LDTM_X32(xr, tmem + (hh * 4 + c4) * 32);
                        asm volatile("tcgen05.wait::ld.sync.aligned;" ::: "memory");
                        const int col0 = n0 + (hh * 4 + c4) * 32;
                        #pragma unroll
                        for (int j = 0; j < 32; ++j)
                            x[c4 * 32 + j] = __uint_as_float(xr[j]) + bias[col0 + j];
                    }
                    float ss = 0.f;
                    #pragma unroll
                    for (int j = 0; j < 128; ++j) ss += x[j] * x[j];
                    const float rn = rsqrtf(ss * (1.f / DHEAD) + 1e-6f);
                    __half* dst = dstb +
                        (((size_t)b * HEADS + head0 + hh) * NTOK + tok) * DHEAD;
                    const float2* rt = g_rtab + (size_t)tok * 64;
                    #pragma unroll
                    for (int p = 0; p < 64; ++p) {
                        float2 t = rt[p];
                        float y0 = x[2*p]     * rn * ws[2*p];
                        float y1 = x[2*p + 1] * rn * ws[2*p + 1];
                        float o0 = (y0 * t.x - y1 * t.y) * sc;
                        float o1 = (y1 * t.x + y0 * t.y) * sc;
                        *(__half2*)(dst + 2*p) = __floats2half2_rn(o0, o1);
                    }
                }
            }
        }
    }
    __syncthreads();
    if (tid < 32) {
        asm volatile("tcgen05.relinquish_alloc_permit.cta_group::1.sync.aligned;");
        asm volatile("tcgen05.dealloc.cta_group::1.sync.aligned.b32 %0, %1;"
                     :: "r"(tmem), "r"(256u));
    }

#else
    // -------- mma.sync fallback (compile-validity on non-'a' passes only) ---
    __half* sh = (__half*)ts;
    const int lane = tid & 31, warp = tid >> 5;
    const int g = lane >> 2, cq = lane & 3;
    const int wm = warp >> 2, wn = warp & 3;
    const int GST = 128 * 40, GSTG = 2 * GST;

    for (int half = 0; half < 2; ++half) {
        const int nh0 = n0 + half * 128;
        const int lrow = tid >> 2, lch = tid & 3;
        const __half* Ag = A + (size_t)(m0 + lrow) * K + lch * 8;
        const __half* Bg = B + (size_t)(nh0 + lrow) * K + lch * 8;

        float acc[4][4][4] = {};

        auto issue = [&](int s, int k0) {
            __half* As = sh + s * GSTG;
            __half* Bs = As + GST;
            uint32_t da = smaddr(As + lrow * 40 + lch * 8);
            uint32_t db = smaddr(Bs + lrow * 40 + lch * 8);
            cpa16(da,            Ag + k0);
            cpa16(da + 64*40*2,  Ag + (size_t)64 * K + k0);
            cpa16(db,            Bg + k0);
            cpa16(db + 64*40*2,  Bg + (size_t)64 * K + k0);
        };

        issue(0, 0);  CP_COMMIT();
        issue(1, 32); CP_COMMIT();
        issue(2, 64); CP_COMMIT();

        const int nk32 = K / 32;
        for (int ks = 0; ks < nk32; ++ks) {
            if (ks == nk32 - 1) { CP_WAIT(0); } else { CP_WAIT(1); }
            __syncthreads();
            if (ks + 3 < nk32) issue((ks + 3) & 3, (ks + 3) * 32);
            CP_COMMIT();

            const __half* As = sh + (ks & 3) * GSTG;
            const __half* Bs = As + GST;
            #pragma unroll
            for (int kk = 0; kk < 2; ++kk) {
                uint32_t af[4][4], bf[4][2];
                #pragma unroll
                for (int mt = 0; mt < 4; ++mt)
                    ldsm4(af[mt][0], af[mt][1], af[mt][2], af[mt][3],
                          smaddr(As + (wm*64 + mt*16 + (lane & 15)) * 40
                                    + kk*16 + (lane >> 4) * 8));
                #pragma unroll
                for (int p = 0; p < 2; ++p)
                    ldsm4(bf[2*p][0], bf[2*p+1][0], bf[2*p][1], bf[2*p+1][1],
                          smaddr(Bs + (wn*32 + p*16 + (lane & 15)) * 40
                                    + kk*16 + (lane >> 4) * 8));
                #pragma unroll
                for (int mt = 0; mt < 4; ++mt)
                    #pragma unroll
                    for (int nt = 0; nt < 4; ++nt)
                        mma16(acc[mt][nt], af[mt], bf[nt]);
            }
            __syncthreads();
        }

        #pragma unroll
        for (int mt = 0; mt < 4; ++mt) {
            int r0 = m0 + wm*64 + mt*16 + g;
            int r1 = r0 + 8;
            #pragma unroll
            for (int nt = 0; nt < 4; ++nt) {
                int col = nh0 + wn*32 + nt*8 + 2*cq;
                float b0 = bias[col], b1 = bias[col + 1];
                float2 v0 = make_float2(acc[mt][nt][0] + b0, acc[mt][nt][1] + b1);
                float2 v1 = make_float2(acc[mt][nt][2] + b0, acc[mt][nt][3] + b1);
                if (MODE == 0) {
                    *(float2*)(C + (size_t)r0 * N + col) = v0;
                    *(float2*)(C + (size_t)r1 * N + col) = v1;
                } else {
                    int part = col / CM;
                    int within = col % CM;
                    int head = within >> 7;
                    int d = within & 127;
                    int b0i = r0 >> 11, t0 = r0 & (NTOK - 1);
                    int b1i = r1 >> 11, t1 = r1 & (NTOK - 1);
                    size_t o0 = (((size_t)b0i * HEADS + head) * NTOK + t0) * DHEAD + d;
                    size_t o1 = (((size_t)b1i * HEADS + head) * NTOK + t1) * DHEAD + d;
                    if (part == 0) {
                        *(float2*)(g_q + o0) = v0; *(float2*)(g_q + o1) = v1;
                    } else if (part == 1) {
                        *(float2*)(g_k + o0) = v0; *(float2*)(g_k + o1) = v1;
                    } else {
                        *(__half2*)(g_v16 + o0) = __floats2half2_rn(v0.x, v0.y);
                        *(__half2*)(g_v16 + o1) = __floats2half2_rn(v1.x, v1.y);
                    }
                }
            }
        }
        __syncthreads();
    }
#endif
}

// ---------------------------------------------------------------------------
// Flash attention, fp16 mma.sync. Br=128 (8 warps x 16 rows), Bc=64.
// Softmax exp via ex2.approx.f16x2 (h2exp2): one MUFU op per PAIR of scores,
// producing the packed fp16 P fragment directly (no h2u packs). Row sums in
// fp32 via __half22float2. alpha rescale factors stay fp32 __expf (2/chunk).
// ---------------------------------------------------------------------------
#define FKV 8704                // 64*136 halves
#define FSTG (2 * FKV)
#define L2E 1.4426950408889634f

__global__ __launch_bounds__(256, 1)
void flash_h()
{
    extern __shared__ __half fsh[];

    const int tid = threadIdx.x, lane = tid & 31, w = tid >> 5;
    const int g = lane >> 2, cq = lane & 3;
    const int q0 = blockIdx.x * 128;
    const size_t hb = ((size_t)blockIdx.z * HEADS + blockIdx.y) * NTOK * DHEAD;
    const __half* Qg = g_q16 + hb + (size_t)q0 * DHEAD;
    const __half* Kg = g_k16 + hb;
    const __half* Vg = g_v16 + hb;

    {
        #pragma unroll
        for (int it = 0; it < 8; ++it) {
            int cid = it * 256 + tid;
            int r = cid >> 4, ch = cid & 15;
            *(uint4*)(fsh + r * 136 + ch * 8) = *(const uint4*)(Qg + r * 128 + ch * 8);
        }
    }
    __syncthreads();
    uint32_t qa[8][4];
    #pragma unroll
    for (int kk = 0; kk < 8; ++kk)
        ldsm4(qa[kk][0], qa[kk][1], qa[kk][2], qa[kk][3],
              smaddr(fsh + (w*16 + (lane & 15)) * 136 + kk*16 + (lane >> 4) * 8));
    __syncthreads();

    auto issueKV = [&](int s, int c0) {
        __half* Kst = fsh + s * FSTG;
        __half* Vst = Kst + FKV;
        const __half* Kp = Kg + (size_t)c0 * DHEAD;
        const __half* Vp = Vg + (size_t)c0 * DHEAD;
        #pragma unroll
        for (int it = 0; it < 4; ++it) {
            int cid = it * 256 + tid;
            int r = cid >> 4, ch = cid & 15;
            cpa16(smaddr(Kst + r * 136 + ch * 8), Kp + r * 128 + ch * 8);
            cpa16(smaddr(Vst + r * 136 + ch * 8), Vp + r * 128 + ch * 8);
        }
    };

    float od[16][4] = {};
    float m0 = -INFINITY, m1 = -INFINITY, l0 = 0.f, l1 = 0.f;

    issueKV(0, 0); CP_COMMIT();

    for (int c = 0; c < NTOK / 64; ++c) {
        if (c + 1 < NTOK / 64) issueKV((c + 1) & 1, (c + 1) * 64);
        CP_COMMIT();
        CP_WAIT(1);
        __syncthreads();

        const __half* Kst = fsh + (c & 1) * FSTG;
        const __half* Vst = Kst + FKV;

        float s[8][4] = {};
        #pragma unroll
        for (int kk = 0; kk < 8; ++kk) {
            uint32_t bf[8][2];
            #pragma unroll
            for (int p = 0; p < 4; ++p)
                ldsm4(bf[2*p][0], bf[2*p+1][0], bf[2*p][1], bf[2*p+1][1],
                      smaddr(Kst + (p*16 + (lane & 15)) * 136
                                 + kk*16 + (lane >> 4) * 8));
            #pragma unroll
            for (int nt = 0; nt < 8; ++nt)
                mma16(s[nt], qa[kk], bf[nt]);
        }

        float cm0 = -INFINITY, cm1 = -INFINITY;
        #pragma unroll
        for (int nt = 0; nt < 8; ++nt) {
            cm0 = fmaxf(cm0, fmaxf(s[nt][0], s[nt][1]));
            cm1 = fmaxf(cm1, fmaxf(s[nt][2], s[nt][3]));
        }
        cm0 = fmaxf(cm0, __shfl_xor_sync(0xffffffffu, cm0, 1));
        cm0 = fmaxf(cm0, __shfl_xor_sync(0xffffffffu, cm0, 2));
        cm1 = fmaxf(cm1, __shfl_xor_sync(0xffffffffu, cm1, 1));
        cm1 = fmaxf(cm1, __shfl_xor_sync(0xffffffffu, cm1, 2));
        float mn0 = fmaxf(m0, cm0), mn1 = fmaxf(m1, cm1);
        float al0 = __expf(m0 - mn0), al1 = __expf(m1 - mn1);
        m0 = mn0; m1 = mn1;

        // exp2 in fp16x2: directly produces packed P fragments
        uint32_t pa[4][4];
        float rs0 = 0.f, rs1 = 0.f;
        #pragma unroll
        for (int nt = 0; nt < 8; ++nt) {
            __half2 t01 = __floats2half2_rn((s[nt][0] - mn0) * L2E,
                                            (s[nt][1] - mn0) * L2E);
            __half2 t23 = __floats2half2_rn((s[nt][2] - mn1) * L2E,
                                            (s[nt][3] - mn1) * L2E);
            __half2 e01 = h2exp2(t01);
            __half2 e23 = h2exp2(t23);
            float2 f01 = __half22float2(e01);
            float2 f23 = __half22float2(e23);
            rs0 += f01.x + f01.y;
            rs1 += f23.x + f23.y;
            pa[nt >> 1][(nt & 1) * 2]     = *(uint32_t*)&e01;
            pa[nt >> 1][(nt & 1) * 2 + 1] = *(uint32_t*)&e23;
        }
        rs0 += __shfl_xor_sync(0xffffffffu, rs0, 1);
        rs0 += __shfl_xor_sync(0xffffffffu, rs0, 2);
        rs1 += __shfl_xor_sync(0xffffffffu, rs1, 1);
        rs1 += __shfl_xor_sync(0xffffffffu, rs1, 2);
        l0 = l0 * al0 + rs0;
        l1 = l1 * al1 + rs1;

        #pragma unroll
        for (int dt = 0; dt < 16; ++dt) {
            od[dt][0] *= al0; od[dt][1] *= al0;
            od[dt][2] *= al1; od[dt][3] *= al1;
        }

        #pragma unroll
        for (int k2 = 0; k2 < 4; ++k2) {
            #pragma unroll
            for (int dp = 0; dp < 8; ++dp) {
                uint32_t v0, v1, v2, v3;
                int t = lane >> 3, r = lane & 7;
                ldsm4t(v0, v1, v2, v3,
                       smaddr(Vst + (k2*16 + (t & 1)*8 + r) * 136
                                  + dp*16 + (t >> 1)*8));
                uint32_t b0[2] = {v0, v1}, b1[2] = {v2, v3};
                mma16(od[2*dp],     pa[k2], b0);
                mma16(od[2*dp + 1], pa[k2], b1);
            }
        }
        __syncthreads();
    }

    float inv0 = 1.f / l0, inv1 = 1.f / l1;
    int r0 = q0 + w*16 + g, r1 = r0 + 8;
    size_t base0 = (((size_t)blockIdx.z * NTOK + r0) * HEADS + blockIdx.y) * DHEAD;
    size_t base1 = (((size_t)blockIdx.z * NTOK + r1) * HEADS + blockIdx.y) * DHEAD;
    #pragma unroll
    for (int dt = 0; dt < 16; ++dt) {
        int col = dt*8 + 2*cq;
        *(__half2*)(g_att16 + base0 + col) =
            __floats2half2_rn(od[dt][0] * inv0, od[dt][1] * inv0);
        *(__half2*)(g_att16 + base1 + col) =
            __floats2half2_rn(od[dt][2] * inv1, od[dt][3] * inv1);
    }
}

// ---------------------------------------------------------------------------
extern "C" void kernel_launch(void* const* d_in, const int* in_sizes, int n_in,
                              void* d_out, int out_size)
{
    const float* x      = (const float*)d_in[0];
    const float* qkv_w  = (const float*)d_in[1];
    const float* qkv_b  = (const float*)d_in[2];
    const float* qn_w   = (const float*)d_in[3];
    const float* kn_w   = (const float*)d_in[4];
    const float* proj_w = (const float*)d_in[5];
    const float* proj_b = (const float*)d_in[6];
    float* out = (float*)d_out;

    __half *x16, *w16, *pw16, *att16;
    cudaGetSymbolAddress((void**)&x16,   g_x16);
    cudaGetSymbolAddress((void**)&w16,   g_w16);
    cudaGetSymbolAddress((void**)&pw16,  g_pw16);
    cudaGetSymbolAddress((void**)&att16, g_att16);

    // 0) fp32 -> fp16 pre-conversion + RoPE cos/sin table
    f2h_kernel<<<1024, 256>>>((const float4*)x,      (uint4*)x16,  MTOT * CM / 8);
    f2h_kernel<<<2048, 256>>>((const float4*)qkv_w,  (uint4*)w16,  3 * CM * CM / 8);
    f2h_kernel<<<1024, 256>>>((const float4*)proj_w, (uint4*)pw16, CM * CM / 8);
    rope_tab_kernel<<<NTOK, 64>>>();

    cudaFuncSetAttribute(gemm_u<1>, cudaFuncAttributeMaxDynamicSharedMemorySize, GEMM_SMEM);
    cudaFuncSetAttribute(gemm_u<0>, cudaFuncAttributeMaxDynamicSharedMemorySize, GEMM_SMEM);
    const int fsm = 2 * FSTG * (int)sizeof(__half);     // 69632 B
    cudaFuncSetAttribute(flash_h, cudaFuncAttributeMaxDynamicSharedMemorySize, fsm);

    // 1) QKV GEMM (cg1) with fused bias+RMSNorm+RoPE epilogue -> q16/k16/v16
    gemm_u<1><<<dim3(3 * CM / 256, MTOT / 128), 256, GEMM_SMEM>>>(
        x16, w16, qkv_b, nullptr, 3 * CM, qn_w, kn_w);

    // 2) Flash attention -> fp16 att [B,N,H,D]
    flash_h<<<dim3(NTOK / 128, HEADS, BATCH), 256, fsm>>>();

    // 3) Output projection (cg1) -> fp32 out
    gemm_u<0><<<dim3(CM / 256, MTOT / 128), 256, GEMM_SMEM>>>(
        att16, pw16, proj_b, out, CM, nullptr, nullptr);
}

// round 14
// speedup vs baseline: 1.0802x; 1.0555x over previous
#include <cuda_runtime.h>
#include <cuda_fp16.h>
#include <math.h>
#include <stdint.h>

#define BATCH 2
#define NTOK  2048
#define HEADS 24
#define DHEAD 128
#define CM    3072
#define MTOT  (BATCH*NTOK)   // 4096

// fp32 scratch — used only by the non-'a' fallback path.
__device__ __align__(256) float g_q[(size_t)BATCH*HEADS*NTOK*DHEAD];
__device__ __align__(256) float g_k[(size_t)BATCH*HEADS*NTOK*DHEAD];
// fp16 scratch
__device__ __align__(256) __half g_x16[(size_t)MTOT*CM];
__device__ __align__(256) __half g_w16[(size_t)3*CM*CM];
__device__ __align__(256) __half g_pw16[(size_t)CM*CM];
__device__ __align__(256) __half g_q16[(size_t)BATCH*HEADS*NTOK*DHEAD];
__device__ __align__(256) __half g_k16[(size_t)BATCH*HEADS*NTOK*DHEAD];
__device__ __align__(256) __half g_v16[(size_t)BATCH*HEADS*NTOK*DHEAD];
__device__ __align__(256) __half g_att16[(size_t)MTOT*CM];
// RoPE cos/sin table: [tok][pair]
__device__ __align__(256) float2 g_rtab[(size_t)NTOK*64];

// ---------------------------------------------------------------------------
// base-ISA helpers
// ---------------------------------------------------------------------------
__device__ __forceinline__ uint32_t smaddr(const void* p) {
    return (uint32_t)__cvta_generic_to_shared(p);
}
__device__ __forceinline__ void ldsm4(uint32_t& r0, uint32_t& r1, uint32_t& r2,
                                      uint32_t& r3, uint32_t a) {
    asm volatile("ldmatrix.sync.aligned.m8n8.x4.shared.b16 {%0,%1,%2,%3},[%4];"
                 : "=r"(r0), "=r"(r1), "=r"(r2), "=r"(r3) : "r"(a));
}
__device__ __forceinline__ void ldsm4t(uint32_t& r0, uint32_t& r1, uint32_t& r2,
                                       uint32_t& r3, uint32_t a) {
    asm volatile("ldmatrix.sync.aligned.m8n8.x4.trans.shared.b16 {%0,%1,%2,%3},[%4];"
                 : "=r"(r0), "=r"(r1), "=r"(r2), "=r"(r3) : "r"(a));
}
__device__ __forceinline__ void mma16(float c[4], const uint32_t a[4], const uint32_t b[2]) {
    asm volatile("mma.sync.aligned.m16n8k16.row.col.f32.f16.f16.f32 "
                 "{%0,%1,%2,%3},{%4,%5,%6,%7},{%8,%9},{%0,%1,%2,%3};"
                 : "+f"(c[0]), "+f"(c[1]), "+f"(c[2]), "+f"(c[3])
                 : "r"(a[0]), "r"(a[1]), "r"(a[2]), "r"(a[3]), "r"(b[0]), "r"(b[1]));
}
__device__ __forceinline__ void cpa16(uint32_t s, const void* g) {
    asm volatile("cp.async.cg.shared.global [%0],[%1],16;" :: "r"(s), "l"(g));
}
#define CP_COMMIT() asm volatile("cp.async.commit_group;")
#define CP_WAIT(n)  asm volatile("cp.async.wait_group %0;" :: "n"(n))
__device__ __forceinline__ uint32_t h2u(float lo, float hi) {
    __half2 h = __floats2half2_rn(lo, hi);
    return *(uint32_t*)&h;
}
__device__ __forceinline__ void mbar_init(uint32_t a, uint32_t c) {
    asm volatile("mbarrier.init.shared.b64 [%0], %1;" :: "r"(a), "r"(c) : "memory");
}
__device__ __forceinline__ void mbar_wait(uint32_t mbar, uint32_t parity) {
    asm volatile("{\n\t.reg .pred P1;\n\t"
                 "W_%=:\n\t"
                 "mbarrier.try_wait.parity.acquire.cta.shared::cta.b64 P1, [%0], %1, 0x989680;\n\t"
                 "@P1 bra.uni D_%=;\n\t"
                 "bra.uni W_%=;\n\t"
                 "D_%=:\n\t}" :: "r"(mbar), "r"(parity) : "memory");
}

#define SMEM_SWIZZLE_128B(o) ((o) ^ (((o) >> 3) & 0x70))

// ---------------------------------------------------------------------------
// tcgen05 helpers — sm_103a ('a' feature) pass only.
// ---------------------------------------------------------------------------
#if defined(__CUDA_ARCH_FEAT_SM103_ALL) || defined(__CUDA_ARCH_FEAT_SM100_ALL)
#define TC_ON 1
static constexpr uint64_t SMEM_DESC_BASE_SW128 =
    (uint64_t(2)  << 61) | (uint64_t(1) << 46) | (uint64_t(64) << 32) | (uint64_t(1) << 16);
__device__ __forceinline__ uint64_t mk_desc(uint32_t a) {
    return SMEM_DESC_BASE_SW128 | ((uint64_t)(a >> 4) & 0x3FFF);
}
__device__ __forceinline__ void mma_f16_ss_cg1(uint32_t d, uint64_t ad, uint64_t bd,
                                               uint32_t idesc, bool acc) {
    uint32_t en = acc ? 1u : 0u;
    asm volatile("{\n\t.reg .pred p;\n\tsetp.ne.u32 p, %4, 0;\n\t"
                 "tcgen05.mma.cta_group::1.kind::f16 [%0], %1, %2, %3, {%5,%5,%5,%5}, p;\n\t}"
                 :: "r"(d), "l"(ad), "l"(bd), "r"(idesc), "r"(en), "r"(0u) : "memory");
}
__device__ __forceinline__ void tc_commit(uint32_t mbar) {
    asm volatile("tcgen05.commit.cta_group::1.mbarrier::arrive::one.shared::cluster.b64 [%0];"
                 :: "r"(mbar) : "memory");
}
#define LDTM_X32(r, addr) \
    asm volatile("tcgen05.ld.sync.aligned.32x32b.x32.b32 " \
        "{%0,%1,%2,%3,%4,%5,%6,%7,%8,%9,%10,%11,%12,%13,%14,%15," \
        "%16,%17,%18,%19,%20,%21,%22,%23,%24,%25,%26,%27,%28,%29,%30,%31},[%32];" \
        : "=r"((r)[0]),"=r"((r)[1]),"=r"((r)[2]),"=r"((r)[3]), \
          "=r"((r)[4]),"=r"((r)[5]),"=r"((r)[6]),"=r"((r)[7]), \
          "=r"((r)[8]),"=r"((r)[9]),"=r"((r)[10]),"=r"((r)[11]), \
          "=r"((r)[12]),"=r"((r)[13]),"=r"((r)[14]),"=r"((r)[15]), \
          "=r"((r)[16]),"=r"((r)[17]),"=r"((r)[18]),"=r"((r)[19]), \
          "=r"((r)[20]),"=r"((r)[21]),"=r"((r)[22]),"=r"((r)[23]), \
          "=r"((r)[24]),"=r"((r)[25]),"=r"((r)[26]),"=r"((r)[27]), \
          "=r"((r)[28]),"=r"((r)[29]),"=r"((r)[30]),"=r"((r)[31]) \
        : "r"(addr))
#endif

// ---------------------------------------------------------------------------
// fp32 -> fp16 converter
// ---------------------------------------------------------------------------
__global__ void f2h_kernel(const float4* __restrict__ src, uint4* __restrict__ dst,
                           int n8)
{
    for (int i = blockIdx.x * blockDim.x + threadIdx.x; i < n8;
         i += gridDim.x * blockDim.x) {
        float4 a = src[2 * i], b = src[2 * i + 1];
        dst[i] = make_uint4(h2u(a.x, a.y), h2u(a.z, a.w), h2u(b.x, b.y), h2u(b.z, b.w));
    }
}

// ---------------------------------------------------------------------------
// RoPE table
// ---------------------------------------------------------------------------
__global__ void rope_tab_kernel()
{
    int idx = blockIdx.x * 64 + threadIdx.x;
    int tok = idx >> 6, p = idx & 63;
    int d = 2 * p;
    float pos, e;
    if (d < 44)      { pos = (float)(tok >> 8);        e = (float)d        * (1.f / 44.f); }
    else if (d < 86) { pos = (float)((tok >> 4) & 15); e = (float)(d - 44) * (1.f / 42.f); }
    else             { pos = (float)(tok & 15);        e = (float)(d - 86) * (1.f / 42.f); }
    float f = expf(-9.210340371976184f * e);
    float cs, sn;
    sincosf(pos * f, &sn, &cs);
    g_rtab[idx] = make_float2(cs, sn);
}

// ---------------------------------------------------------------------------
// Unified GEMM-NT (cg1, round-9 proven): C = A·B^T + bias, K = 3072.
// Grid (N/256, M/128), 256 threads. tcgen05 f16 SS, BM=128 BN=256 BK=64,
// 4-stage cp.async, one commit group per iter; CP_WAIT(2) retires chunk ks.
// MODE 0: fp32 C. MODE 1: QKV epilogue with fused rope/rms (q,k), bias (v).
// ---------------------------------------------------------------------------
#define TSTAGE  49152            // A 16KB + B 32KB per stage
#define TAB     16384
#define GEMM_SMEM (3072 + 4 * TSTAGE)

template<int MODE>
__global__ __launch_bounds__(256, 1)
void gemm_u(const __half* __restrict__ A, const __half* __restrict__ B,
            const float* __restrict__ bias, float* __restrict__ C, int N,
            const float* __restrict__ qn_w, const float* __restrict__ kn_w)
{
    extern __shared__ char ts[];
    const int tid = threadIdx.x;
    const int K = 3072, nk = 48;
    const int n0 = blockIdx.x * 256, m0 = blockIdx.y * 128;

#if defined(TC_ON)
    const uint32_t sb = smaddr(ts);
    const uint32_t ab = (sb + 2048 + 1023) & ~1023u;
    const uint32_t tmem_ptr_addr = sb;
    const uint32_t mbs0 = sb + 8;
    float* wsm = (float*)ts + 64;

    if (tid < 32)
        asm volatile("tcgen05.alloc.cta_group::1.sync.aligned.shared::cta.b32 [%0], %1;"
                     :: "r"(tmem_ptr_addr), "r"(256u) : "memory");
    if (tid == 0)
        for (int i = 0; i < 4; ++i) mbar_init(mbs0 + 8 * i, 1);
    if (MODE == 1) {
        if (tid < 128) wsm[tid] = qn_w[tid];
        else           wsm[tid] = kn_w[tid - 128];
    }
    __syncthreads();
    uint32_t tmem;
    asm volatile("ld.shared.b32 %0,[%1];" : "=r"(tmem) : "r"(tmem_ptr_addr));

    const __half* Agb = A + (size_t)m0 * K;
    const __half* Bgb = B + (size_t)n0 * K;

    auto fill = [&](int s, int kc) {
        uint32_t base = ab + s * TSTAGE;
        const __half* Agp = Agb + kc * 64;
        const __half* Bgp = Bgb + kc * 64;
        #pragma unroll
        for (int it = 0; it < 4; ++it) {
            int idx = it * 256 + tid;
            int r = idx >> 3, ch = idx & 7;
            cpa16(base + SMEM_SWIZZLE_128B(r * 128 + ch * 16),
                  Agp + (size_t)r * K + ch * 8);
        }
        #pragma unroll
        for (int it = 0; it < 8; ++it) {
            int idx = it * 256 + tid;
            int r = idx >> 3, ch = idx & 7;
            cpa16(base + TAB + SMEM_SWIZZLE_128B(r * 128 + ch * 16),
                  Bgp + (size_t)r * K + ch * 8);
        }
        CP_COMMIT();
    };

    fill(0, 0); fill(1, 1); fill(2, 2);

    const uint32_t idesc = (1u << 4) | (32u << 17) | (8u << 24);
    int ph[4] = {0, 0, 0, 0};

    for (int ks = 0; ks < nk; ++ks) {
        const int s = ks & 3;
        CP_WAIT(2);
        __syncthreads();

        if (tid == 0) {
            asm volatile("fence.proxy.async.shared::cta;" ::: "memory");
            uint32_t base = ab + s * TSTAGE;
            uint64_t ad = mk_desc(base);
            uint64_t bd = mk_desc(base + TAB);
            #pragma unroll
            for (int sub = 0; sub < 4; ++sub)
                mma_f16_ss_cg1(tmem, ad + sub * 2, bd + sub * 2, idesc,
                               (ks > 0) || (sub > 0));
            tc_commit(mbs0 + 8 * s);
        }

        if (ks + 3 < nk) {
            const int nxt = (ks + 3) & 3;
            if (ks >= 1) {
                mbar_wait(mbs0 + 8 * nxt, ph[nxt]);
                ph[nxt] ^= 1;
            }
            fill(nxt, ks + 3);
        } else {
            CP_COMMIT();
        }
    }

    {
        const int sl = (nk - 1) & 3;
        mbar_wait(mbs0 + 8 * sl, ph[sl]);
    }
    asm volatile("tcgen05.fence::after_thread_sync;" ::: "memory");
    __syncthreads();

    const int w = tid >> 5, lane = tid & 31;
    if (w < 4) {
        const int row = m0 + w * 32 + lane;
        if (MODE == 0) {
            #pragma unroll
            for (int chunk = 0; chunk < 8; ++chunk) {
                uint32_t dr[32];
                LDTM_X32(dr, tmem + chunk * 32);
                asm volatile("tcgen05.wait::ld.sync.aligned;" ::: "memory");
                const int col0 = n0 + chunk * 32;
                float* Crow = C + (size_t)row * N + col0;
                #pragma unroll
                for (int j = 0; j < 32; j += 4) {
                    float4 v = make_float4(__uint_as_float(dr[j])   + bias[col0 + j],
                                           __uint_as_float(dr[j+1]) + bias[col0 + j + 1],
                                           __uint_as_float(dr[j+2]) + bias[col0 + j + 2],
                                           __uint_as_float(dr[j+3]) + bias[col0 + j + 3]);
                    *(float4*)(Crow + j) = v;
                }
            }
        } else {
            const int part = n0 / CM;
            const int head0 = (n0 % CM) >> 7;
            const int b = row >> 11, tok = row & (NTOK - 1);
            if (part == 2) {
                #pragma unroll
                for (int chunk = 0; chunk < 8; ++chunk) {
                    uint32_t dr[32];
                    LDTM_X32(dr, tmem + chunk * 32);
                    asm volatile("tcgen05.wait::ld.sync.aligned;" ::: "memory");
                    const int col0 = n0 + chunk * 32;
                    const int head = head0 + (chunk >> 2), d0 = (chunk & 3) * 32;
                    __half* dst = g_v16 +
                        (((size_t)b * HEADS + head) * NTOK + tok) * DHEAD + d0;
                    #pragma unroll
                    for (int j = 0; j < 32; j += 2)
                        *(__half2*)(dst + j) = __floats2half2_rn(
                            __uint_as_float(dr[j])   + bias[col0 + j],
                            __uint_as_float(dr[j+1]) + bias[col0 + j + 1]);
                }
            } else {
                const float* ws = (part == 0) ? wsm : wsm + 128;
                const float sc = (part == 0) ? 0.08838834764831845f : 1.0f;
                __half* dstb = (part == 0) ? g_q16 : g_k16;
                #pragma unroll
                for (int hh = 0; hh < 2; ++hh) {
                    float x[128];
                    #pragma unroll
                    for (int c4 = 0; c4 < 4; ++c4) {
                        uint32_t* xr = (uint32_t*)&x[c4 * 32];
                        LDTM_X32(xr, tmem + (hh * 4 + c4) * 32);
                        asm volatile("tcgen05.wait::ld.sync.aligned;" ::: "memory");
                        const int col0 = n0 + (hh * 4 + c4) * 32;
                        #pragma unroll
                        for (int j = 0; j < 32; ++j)
                            x[c4 * 32 + j] = __uint_as_float(xr[j]) + bias[col0 + j];
                    }
                    float ss = 0.f;
                    #pragma unroll
                    for (int j = 0; j < 128; ++j) ss += x[j] * x[j];
                    const float rn = rsqrtf(ss * (1.f / DHEAD) + 1e-6f);
                    __half* dst = dstb +
                        (((size_t)b * HEADS + head0 + hh) * NTOK + tok) * DHEAD;
                    const float2* rt = g_rtab + (size_t)tok * 64;
                    #pragma unroll
                    for (int p = 0; p < 64; ++p) {
                        float2 t = rt[p];
                        float y0 = x[2*p]     * rn * ws[2*p];
                        float y1 = x[2*p + 1] * rn * ws[2*p + 1];
                        float o0 = (y0 * t.x - y1 * t.y) * sc;
                        float o1 = (y1 * t.x + y0 * t.y) * sc;
                        *(__half2*)(dst + 2*p) = __floats2half2_rn(o0, o1);
                    }
                }
            }
        }
    }
    __syncthreads();
    if (tid < 32) {
        asm volatile("tcgen05.relinquish_alloc_permit.cta_group::1.sync.aligned;");
        asm volatile("tcgen05.dealloc.cta_group::1.sync.aligned.b32 %0, %1;"
                     :: "r"(tmem), "r"(256u));
    }

#else
    // -------- mma.sync fallback (compile-validity on non-'a' passes only) ---
    __half* sh = (__half*)ts;
    const int lane = tid & 31, warp = tid >> 5;
    const int g = lane >> 2, cq = lane & 3;
    const int wm = warp >> 2, wn = warp & 3;
    const int GST = 128 * 40, GSTG = 2 * GST;

    for (int half = 0; half < 2; ++half) {
        const int nh0 = n0 + half * 128;
        const int lrow = tid >> 2, lch = tid & 3;
        const __half* Ag = A + (size_t)(m0 + lrow) * K + lch * 8;
        const __half* Bg = B + (size_t)(nh0 + lrow) * K + lch * 8;

        float acc[4][4][4] = {};

        auto issue = [&](int s, int k0) {
            __half* As = sh + s * GSTG;
            __half* Bs = As + GST;
            uint32_t da = smaddr(As + lrow * 40 + lch * 8);
            uint32_t db = smaddr(Bs + lrow * 40 + lch * 8);
            cpa16(da,            Ag + k0);
            cpa16(da + 64*40*2,  Ag + (size_t)64 * K + k0);
            cpa16(db,            Bg + k0);
            cpa16(db + 64*40*2,  Bg + (size_t)64 * K + k0);
        };

        issue(0, 0);  CP_COMMIT();
        issue(1, 32); CP_COMMIT();
        issue(2, 64); CP_COMMIT();

        const int nk32 = K / 32;
        for (int ks = 0; ks < nk32; ++ks) {
            if (ks == nk32 - 1) { CP_WAIT(0); } else { CP_WAIT(1); }
            __syncthreads();
            if (ks + 3 < nk32) issue((ks + 3) & 3, (ks + 3) * 32);
            CP_COMMIT();

            const __half* As = sh + (ks & 3) * GSTG;
            const __half* Bs = As + GST;
            #pragma unroll
            for (int kk = 0; kk < 2; ++kk) {
                uint32_t af[4][4], bf[4][2];
                #pragma unroll
                for (int mt = 0; mt < 4; ++mt)
                    ldsm4(af[mt][0], af[mt][1], af[mt][2], af[mt][3],
                          smaddr(As + (wm*64 + mt*16 + (lane & 15)) * 40
                                    + kk*16 + (lane >> 4) * 8));
                #pragma unroll
                for (int p = 0; p < 2; ++p)
                    ldsm4(bf[2*p][0], bf[2*p+1][0], bf[2*p][1], bf[2*p+1][1],
                          smaddr(Bs + (wn*32 + p*16 + (lane & 15)) * 40
                                    + kk*16 + (lane >> 4) * 8));
                #pragma unroll
                for (int mt = 0; mt < 4; ++mt)
                    #pragma unroll
                    for (int nt = 0; nt < 4; ++nt)
                        mma16(acc[mt][nt], af[mt], bf[nt]);
            }
            __syncthreads();
        }

        #pragma unroll
        for (int mt = 0; mt < 4; ++mt) {
            int r0 = m0 + wm*64 + mt*16 + g;
            int r1 = r0 + 8;
            #pragma unroll
            for (int nt = 0; nt < 4; ++nt) {
                int col = nh0 + wn*32 + nt*8 + 2*cq;
                float b0 = bias[col], b1 = bias[col + 1];
                float2 v0 = make_float2(acc[mt][nt][0] + b0, acc[mt][nt][1] + b1);
                float2 v1 = make_float2(acc[mt][nt][2] + b0, acc[mt][nt][3] + b1);
                if (MODE == 0) {
                    *(float2*)(C + (size_t)r0 * N + col) = v0;
                    *(float2*)(C + (size_t)r1 * N + col) = v1;
                } else {
                    int part = col / CM;
                    int within = col % CM;
                    int head = within >> 7;
                    int d = within & 127;
                    int b0i = r0 >> 11, t0 = r0 & (NTOK - 1);
                    int b1i = r1 >> 11, t1 = r1 & (NTOK - 1);
                    size_t o0 = (((size_t)b0i * HEADS + head) * NTOK + t0) * DHEAD + d;
                    size_t o1 = (((size_t)b1i * HEADS + head) * NTOK + t1) * DHEAD + d;
                    if (part == 0) {
                        *(float2*)(g_q + o0) = v0; *(float2*)(g_q + o1) = v1;
                    } else if (part == 1) {
                        *(float2*)(g_k + o0) = v0; *(float2*)(g_k + o1) = v1;
                    } else {
                        *(__half2*)(g_v16 + o0) = __floats2half2_rn(v0.x, v0.y);
                        *(__half2*)(g_v16 + o1) = __floats2half2_rn(v1.x, v1.y);
                    }
                }
            }
        }
        __syncthreads();
    }
#endif
}

// ---------------------------------------------------------------------------
// Flash attention, fp16 mma.sync. Br=128 (8 warps x 16 rows), Bc=64.
// NO-MAX softmax: q,k are RMS-normed so s <= sqrt(128) = 11.32 provably;
// p = exp2(s*log2e - 8) <= 318 < fp16 max. Softmax is shift-invariant, so
// this is exact — and deletes the online max/alpha/rescale machinery.
// l accumulated per-thread; single cross-lane reduction at the end.
// 3-stage K/V cp.async pipeline (104 KB smem).
// ---------------------------------------------------------------------------
#define FKV 8704                // 64*136 halves
#define FSTG (2 * FKV)          // K+V per stage (halves)
#define FLASH_SMEM (3 * FSTG * 2)   // 104448 B
#define L2E 1.4426950408889634f

__global__ __launch_bounds__(256, 1)
void flash_h()
{
    extern __shared__ __half fsh[];

    const int tid = threadIdx.x, lane = tid & 31, w = tid >> 5;
    const int g = lane >> 2, cq = lane & 3;
    const int q0 = blockIdx.x * 128;
    const size_t hb = ((size_t)blockIdx.z * HEADS + blockIdx.y) * NTOK * DHEAD;
    const __half* Qg = g_q16 + hb + (size_t)q0 * DHEAD;
    const __half* Kg = g_k16 + hb;
    const __half* Vg = g_v16 + hb;

    {   // stage Q through stage-0 area, pull register fragments
        #pragma unroll
        for (int it = 0; it < 8; ++it) {
            int cid = it * 256 + tid;
            int r = cid >> 4, ch = cid & 15;
            *(uint4*)(fsh + r * 136 + ch * 8) = *(const uint4*)(Qg + r * 128 + ch * 8);
        }
    }
    __syncthreads();
    uint32_t qa[8][4];
    #pragma unroll
    for (int kk = 0; kk < 8; ++kk)
        ldsm4(qa[kk][0], qa[kk][1], qa[kk][2], qa[kk][3],
              smaddr(fsh + (w*16 + (lane & 15)) * 136 + kk*16 + (lane >> 4) * 8));
    __syncthreads();

    auto issueKV = [&](int s, int c0) {
        __half* Kst = fsh + s * FSTG;
        __half* Vst = Kst + FKV;
        const __half* Kp = Kg + (size_t)c0 * 64 * DHEAD;
        const __half* Vp = Vg + (size_t)c0 * 64 * DHEAD;
        #pragma unroll
        for (int it = 0; it < 4; ++it) {
            int cid = it * 256 + tid;
            int r = cid >> 4, ch = cid & 15;
            cpa16(smaddr(Kst + r * 136 + ch * 8), Kp + r * 128 + ch * 8);
            cpa16(smaddr(Vst + r * 136 + ch * 8), Vp + r * 128 + ch * 8);
        }
        CP_COMMIT();
    };

    float od[16][4] = {};
    float l0 = 0.f, l1 = 0.f;

    issueKV(0, 0);      // group 0 = chunk 0
    issueKV(1, 1);      // group 1 = chunk 1

    const int nc = NTOK / 64;   // 32
    for (int c = 0; c < nc; ++c) {
        // one commit group per iteration (ledger: at top of iter c, groups
        // 0..c+1 committed; after this line 0..c+2; CP_WAIT(2) retires chunk c)
        if (c + 2 < nc) issueKV((c + 2) % 3, c + 2);
        else            CP_COMMIT();
        CP_WAIT(2);
        __syncthreads();

        const __half* Kst = fsh + (c % 3) * FSTG;
        const __half* Vst = Kst + FKV;

        // S = Q.K^T
        float s[8][4] = {};
        #pragma unroll
        for (int kk = 0; kk < 8; ++kk) {
            uint32_t bf[8][2];
            #pragma unroll
            for (int p = 0; p < 4; ++p)
                ldsm4(bf[2*p][0], bf[2*p+1][0], bf[2*p][1], bf[2*p+1][1],
                      smaddr(Kst + (p*16 + (lane & 15)) * 136
                                 + kk*16 + (lane >> 4) * 8));
            #pragma unroll
            for (int nt = 0; nt < 8; ++nt)
                mma16(s[nt], qa[kk], bf[nt]);
        }

        // p = exp2(s*log2e - 8); pack straight into A-fragments; partial sums
        uint32_t pa[4][4];
        float rs0 = 0.f, rs1 = 0.f;
        #pragma unroll
        for (int nt = 0; nt < 8; ++nt) {
            float p0 = exp2f(fmaf(s[nt][0], L2E, -8.f));
            float p1 = exp2f(fmaf(s[nt][1], L2E, -8.f));
            float p2 = exp2f(fmaf(s[nt][2], L2E, -8.f));
            float p3 = exp2f(fmaf(s[nt][3], L2E, -8.f));
            rs0 += p0 + p1;
            rs1 += p2 + p3;
            pa[nt >> 1][(nt & 1) * 2]     = h2u(p0, p1);
            pa[nt >> 1][(nt & 1) * 2 + 1] = h2u(p2, p3);
        }
        l0 += rs0;
        l1 += rs1;

        // O += P.V
        #pragma unroll
        for (int k2 = 0; k2 < 4; ++k2) {
            #pragma unroll
            for (int dp = 0; dp < 8; ++dp) {
                uint32_t v0, v1, v2, v3;
                int t = lane >> 3, r = lane & 7;
                ldsm4t(v0, v1, v2, v3,
                       smaddr(Vst + (k2*16 + (t & 1)*8 + r) * 136
                                  + dp*16 + (t >> 1)*8));
                uint32_t b0[2] = {v0, v1}, b1[2] = {v2, v3};
                mma16(od[2*dp],     pa[k2], b0);
                mma16(od[2*dp + 1], pa[k2], b1);
            }
        }
        __syncthreads();
    }

    // single cross-lane reduction of l (4 lanes share each row)
    l0 += __shfl_xor_sync(0xffffffffu, l0, 1);
    l0 += __shfl_xor_sync(0xffffffffu, l0, 2);
    l1 += __shfl_xor_sync(0xffffffffu, l1, 1);
    l1 += __shfl_xor_sync(0xffffffffu, l1, 2);

    float inv0 = 1.f / l0, inv1 = 1.f / l1;
    int r0 = q0 + w*16 + g, r1 = r0 + 8;
    size_t base0 = (((size_t)blockIdx.z * NTOK + r0) * HEADS + blockIdx.y) * DHEAD;
    size_t base1 = (((size_t)blockIdx.z * NTOK + r1) * HEADS + blockIdx.y) * DHEAD;
    #pragma unroll
    for (int dt = 0; dt < 16; ++dt) {
        int col = dt*8 + 2*cq;
        *(__half2*)(g_att16 + base0 + col) =
            __floats2half2_rn(od[dt][0] * inv0, od[dt][1] * inv0);
        *(__half2*)(g_att16 + base1 + col) =
            __floats2half2_rn(od[dt][2] * inv1, od[dt][3] * inv1);
    }
}

// ---------------------------------------------------------------------------
extern "C" void kernel_launch(void* const* d_in, const int* in_sizes, int n_in,
                              void* d_out, int out_size)
{
    const float* x      = (const float*)d_in[0];
    const float* qkv_w  = (const float*)d_in[1];
    const float* qkv_b  = (const float*)d_in[2];
    const float* qn_w   = (const float*)d_in[3];
    const float* kn_w   = (const float*)d_in[4];
    const float* proj_w = (const float*)d_in[5];
    const float* proj_b = (const float*)d_in[6];
    float* out = (float*)d_out;

    __half *x16, *w16, *pw16, *att16;
    cudaGetSymbolAddress((void**)&x16,   g_x16);
    cudaGetSymbolAddress((void**)&w16,   g_w16);
    cudaGetSymbolAddress((void**)&pw16,  g_pw16);
    cudaGetSymbolAddress((void**)&att16, g_att16);

    // 0) fp32 -> fp16 pre-conversion + RoPE cos/sin table
    f2h_kernel<<<1024, 256>>>((const float4*)x,      (uint4*)x16,  MTOT * CM / 8);
    f2h_kernel<<<2048, 256>>>((const float4*)qkv_w,  (uint4*)w16,  3 * CM * CM / 8);
    f2h_kernel<<<1024, 256>>>((const float4*)proj_w, (uint4*)pw16, CM * CM / 8);
    rope_tab_kernel<<<NTOK, 64>>>();

    cudaFuncSetAttribute(gemm_u<1>, cudaFuncAttributeMaxDynamicSharedMemorySize, GEMM_SMEM);
    cudaFuncSetAttribute(gemm_u<0>, cudaFuncAttributeMaxDynamicSharedMemorySize, GEMM_SMEM);
    cudaFuncSetAttribute(flash_h, cudaFuncAttributeMaxDynamicSharedMemorySize, FLASH_SMEM);

    // 1) QKV GEMM (cg1) with fused bias+RMSNorm+RoPE epilogue -> q16/k16/v16
    gemm_u<1><<<dim3(3 * CM / 256, MTOT / 128), 256, GEMM_SMEM>>>(
        x16, w16, qkv_b, nullptr, 3 * CM, qn_w, kn_w);

    // 2) Flash attention -> fp16 att [B,N,H,D]
    flash_h<<<dim3(NTOK / 128, HEADS, BATCH), 256, FLASH_SMEM>>>();

    // 3) Output projection (cg1) -> fp32 out
    gemm_u<0><<<dim3(CM / 256, MTOT / 128), 256, GEMM_SMEM>>>(
        att16, pw16, proj_b, out, CM, nullptr, nullptr);
}

// round 16
// speedup vs baseline: 1.1205x; 1.0373x over previous
#include <cuda_runtime.h>
#include <cuda_fp16.h>
#include <math.h>
#include <stdint.h>

#define BATCH 2
#define NTOK  2048
#define HEADS 24
#define DHEAD 128
#define CM    3072
#define MTOT  (BATCH*NTOK)   // 4096

// fp32 scratch — used only by the non-'a' fallback path.
__device__ __align__(256) float g_q[(size_t)BATCH*HEADS*NTOK*DHEAD];
__device__ __align__(256) float g_k[(size_t)BATCH*HEADS*NTOK*DHEAD];
// fp16 scratch
__device__ __align__(256) __half g_x16[(size_t)MTOT*CM];
__device__ __align__(256) __half g_w16[(size_t)3*CM*CM];
__device__ __align__(256) __half g_pw16[(size_t)CM*CM];
__device__ __align__(256) __half g_q16[(size_t)BATCH*HEADS*NTOK*DHEAD];
__device__ __align__(256) __half g_k16[(size_t)BATCH*HEADS*NTOK*DHEAD];
__device__ __align__(256) __half g_v16[(size_t)BATCH*HEADS*NTOK*DHEAD];
__device__ __align__(256) __half g_att16[(size_t)MTOT*CM];
// RoPE cos/sin table: [tok][pair]
__device__ __align__(256) float2 g_rtab[(size_t)NTOK*64];

// ---------------------------------------------------------------------------
// base-ISA helpers
// ---------------------------------------------------------------------------
__device__ __forceinline__ uint32_t smaddr(const void* p) {
    return (uint32_t)__cvta_generic_to_shared(p);
}
__device__ __forceinline__ void ldsm4(uint32_t& r0, uint32_t& r1, uint32_t& r2,
                                      uint32_t& r3, uint32_t a) {
    asm volatile("ldmatrix.sync.aligned.m8n8.x4.shared.b16 {%0,%1,%2,%3},[%4];"
                 : "=r"(r0), "=r"(r1), "=r"(r2), "=r"(r3) : "r"(a));
}
__device__ __forceinline__ void ldsm4t(uint32_t& r0, uint32_t& r1, uint32_t& r2,
                                       uint32_t& r3, uint32_t a) {
    asm volatile("ldmatrix.sync.aligned.m8n8.x4.trans.shared.b16 {%0,%1,%2,%3},[%4];"
                 : "=r"(r0), "=r"(r1), "=r"(r2), "=r"(r3) : "r"(a));
}
__device__ __forceinline__ void mma16(float c[4], const uint32_t a[4], const uint32_t b[2]) {
    asm volatile("mma.sync.aligned.m16n8k16.row.col.f32.f16.f16.f32 "
                 "{%0,%1,%2,%3},{%4,%5,%6,%7},{%8,%9},{%0,%1,%2,%3};"
                 : "+f"(c[0]), "+f"(c[1]), "+f"(c[2]), "+f"(c[3])
                 : "r"(a[0]), "r"(a[1]), "r"(a[2]), "r"(a[3]), "r"(b[0]), "r"(b[1]));
}
__device__ __forceinline__ void cpa16(uint32_t s, const void* g) {
    asm volatile("cp.async.cg.shared.global [%0],[%1],16;" :: "r"(s), "l"(g));
}
#define CP_COMMIT() asm volatile("cp.async.commit_group;")
#define CP_WAIT(n)  asm volatile("cp.async.wait_group %0;" :: "n"(n))
__device__ __forceinline__ uint32_t h2u(float lo, float hi) {
    __half2 h = __floats2half2_rn(lo, hi);
    return *(uint32_t*)&h;
}
__device__ __forceinline__ void mbar_init(uint32_t a, uint32_t c) {
    asm volatile("mbarrier.init.shared.b64 [%0], %1;" :: "r"(a), "r"(c) : "memory");
}
__device__ __forceinline__ void mbar_wait(uint32_t mbar, uint32_t parity) {
    asm volatile("{\n\t.reg .pred P1;\n\t"
                 "W_%=:\n\t"
                 "mbarrier.try_wait.parity.acquire.cta.shared::cta.b64 P1, [%0], %1, 0x989680;\n\t"
                 "@P1 bra.uni D_%=;\n\t"
                 "bra.uni W_%=;\n\t"
                 "D_%=:\n\t}" :: "r"(mbar), "r"(parity) : "memory");
}

#define SMEM_SWIZZLE_128B(o) ((o) ^ (((o) >> 3) & 0x70))

// ---------------------------------------------------------------------------
// tcgen05 helpers — sm_103a ('a' feature) pass only.
// ---------------------------------------------------------------------------
#if defined(__CUDA_ARCH_FEAT_SM103_ALL) || defined(__CUDA_ARCH_FEAT_SM100_ALL)
#define TC_ON 1
static constexpr uint64_t SMEM_DESC_BASE_SW128 =
    (uint64_t(2)  << 61) | (uint64_t(1) << 46) | (uint64_t(64) << 32) | (uint64_t(1) << 16);
__device__ __forceinline__ uint64_t mk_desc(uint32_t a) {
    return SMEM_DESC_BASE_SW128 | ((uint64_t)(a >> 4) & 0x3FFF);
}
__device__ __forceinline__ void mma_f16_ss_cg1(uint32_t d, uint64_t ad, uint64_t bd,
                                               uint32_t idesc, bool acc) {
    uint32_t en = acc ? 1u : 0u;
    asm volatile("{\n\t.reg .pred p;\n\tsetp.ne.u32 p, %4, 0;\n\t"
                 "tcgen05.mma.cta_group::1.kind::f16 [%0], %1, %2, %3, {%5,%5,%5,%5}, p;\n\t}"
                 :: "r"(d), "l"(ad), "l"(bd), "r"(idesc), "r"(en), "r"(0u) : "memory");
}
__device__ __forceinline__ void tc_commit(uint32_t mbar) {
    asm volatile("tcgen05.commit.cta_group::1.mbarrier::arrive::one.shared::cluster.b64 [%0];"
                 :: "r"(mbar) : "memory");
}
#define LDTM_X32(r, addr) \
    asm volatile("tcgen05.ld.sync.aligned.32x32b.x32.b32 " \
        "{%0,%1,%2,%3,%4,%5,%6,%7,%8,%9,%10,%11,%12,%13,%14,%15," \
        "%16,%17,%18,%19,%20,%21,%22,%23,%24,%25,%26,%27,%28,%29,%30,%31},[%32];" \
        : "=r"((r)[0]),"=r"((r)[1]),"=r"((r)[2]),"=r"((r)[3]), \
          "=r"((r)[4]),"=r"((r)[5]),"=r"((r)[6]),"=r"((r)[7]), \
          "=r"((r)[8]),"=r"((r)[9]),"=r"((r)[10]),"=r"((r)[11]), \
          "=r"((r)[12]),"=r"((r)[13]),"=r"((r)[14]),"=r"((r)[15]), \
          "=r"((r)[16]),"=r"((r)[17]),"=r"((r)[18]),"=r"((r)[19]), \
          "=r"((r)[20]),"=r"((r)[21]),"=r"((r)[22]),"=r"((r)[23]), \
          "=r"((r)[24]),"=r"((r)[25]),"=r"((r)[26]),"=r"((r)[27]), \
          "=r"((r)[28]),"=r"((r)[29]),"=r"((r)[30]),"=r"((r)[31]) \
        : "r"(addr))
#endif

// ---------------------------------------------------------------------------
// fp32 -> fp16 converter (plain)
// ---------------------------------------------------------------------------
__global__ void f2h_kernel(const float4* __restrict__ src, uint4* __restrict__ dst,
                           int n8)
{
    for (int i = blockIdx.x * blockDim.x + threadIdx.x; i < n8;
         i += gridDim.x * blockDim.x) {
        float4 a = src[2 * i], b = src[2 * i + 1];
        dst[i] = make_uint4(h2u(a.x, a.y), h2u(a.z, a.w), h2u(b.x, b.y), h2u(b.z, b.w));
    }
}

// ---------------------------------------------------------------------------
// qkv-weight converter + RoPE table in one launch.
// Blocks [0, WBLK): grid-stride f2h over qkv_w. Blocks [WBLK, WBLK+512): rope.
// ---------------------------------------------------------------------------
#define WBLK 2048
__global__ void f2h_w_rope_kernel(const float4* __restrict__ src,
                                  uint4* __restrict__ dst, int n8)
{
    if (blockIdx.x < WBLK) {
        for (int i = blockIdx.x * blockDim.x + threadIdx.x; i < n8;
             i += WBLK * blockDim.x) {
            float4 a = src[2 * i], b = src[2 * i + 1];
            dst[i] = make_uint4(h2u(a.x, a.y), h2u(a.z, a.w),
                                h2u(b.x, b.y), h2u(b.z, b.w));
        }
    } else {
        int idx = (blockIdx.x - WBLK) * 256 + threadIdx.x;   // 512*256 = 131072
        int tok = idx >> 6, p = idx & 63;
        int d = 2 * p;
        float pos, e;
        if (d < 44)      { pos = (float)(tok >> 8);        e = (float)d        * (1.f / 44.f); }
        else if (d < 86) { pos = (float)((tok >> 4) & 15); e = (float)(d - 44) * (1.f / 42.f); }
        else             { pos = (float)(tok & 15);        e = (float)(d - 86) * (1.f / 42.f); }
        float f = expf(-9.210340371976184f * e);
        float cs, sn;
        sincosf(pos * f, &sn, &cs);
        g_rtab[idx] = make_float2(cs, sn);
    }
}

// ---------------------------------------------------------------------------
// Unified GEMM-NT (cg1, proven): C = A·B^T + bias, K = 3072.
// Grid (N/256, M/128), 256 threads. tcgen05 f16 SS, BM=128 BN=256 BK=64,
// 4-stage cp.async, one commit group per iter; CP_WAIT(2) retires chunk ks.
// MODE 0: fp32 C. MODE 1: QKV epilogue with fused rope/rms (q,k), bias (v).
// ---------------------------------------------------------------------------
#define TSTAGE  49152            // A 16KB + B 32KB per stage
#define TAB     16384
#define GEMM_SMEM (3072 + 4 * TSTAGE)

template<int MODE>
__global__ __launch_bounds__(256, 1)
void gemm_u(const __half* __restrict__ A, const __half* __restrict__ B,
            const float* __restrict__ bias, float* __restrict__ C, int N,
            const float* __restrict__ qn_w, const float* __restrict__ kn_w)
{
    extern __shared__ char ts[];
    const int tid = threadIdx.x;
    const int K = 3072, nk = 48;
    const int n0 = blockIdx.x * 256, m0 = blockIdx.y * 128;

#if defined(TC_ON)
    const uint32_t sb = smaddr(ts);
    const uint32_t ab = (sb + 2048 + 1023) & ~1023u;
    const uint32_t tmem_ptr_addr = sb;
    const uint32_t mbs0 = sb + 8;
    float* wsm = (float*)ts + 64;

    if (tid < 32)
        asm volatile("tcgen05.alloc.cta_group::1.sync.aligned.shared::cta.b32 [%0], %1;"
                     :: "r"(tmem_ptr_addr), "r"(256u) : "memory");
    if (tid == 0)
        for (int i = 0; i < 4; ++i) mbar_init(mbs0 + 8 * i, 1);
    if (MODE == 1) {
        if (tid < 128) wsm[tid] = qn_w[tid];
        else           wsm[tid] = kn_w[tid - 128];
    }
    __syncthreads();
    uint32_t tmem;
    asm volatile("ld.shared.b32 %0,[%1];" : "=r"(tmem) : "r"(tmem_ptr_addr));

    const __half* Agb = A + (size_t)m0 * K;
    const __half* Bgb = B + (size_t)n0 * K;

    auto fill = [&](int s, int kc) {
        uint32_t base = ab + s * TSTAGE;
        const __half* Agp = Agb + kc * 64;
        const __half* Bgp = Bgb + kc * 64;
        #pragma unroll
        for (int it = 0; it < 4; ++it) {
            int idx = it * 256 + tid;
            int r = idx >> 3, ch = idx & 7;
            cpa16(base + SMEM_SWIZZLE_128B(r * 128 + ch * 16),
                  Agp + (size_t)r * K + ch * 8);
        }
        #pragma unroll
        for (int it = 0; it < 8; ++it) {
            int idx = it * 256 + tid;
            int r = idx >> 3, ch = idx & 7;
            cpa16(base + TAB + SMEM_SWIZZLE_128B(r * 128 + ch * 16),
                  Bgp + (size_t)r * K + ch * 8);
        }
        CP_COMMIT();
    };

    fill(0, 0); fill(1, 1); fill(2, 2);

    const uint32_t idesc = (1u << 4) | (32u << 17) | (8u << 24);
    int ph[4] = {0, 0, 0, 0};

    for (int ks = 0; ks < nk; ++ks) {
        const int s = ks & 3;
        CP_WAIT(2);
        __syncthreads();

        if (tid == 0) {
            asm volatile("fence.proxy.async.shared::cta;" ::: "memory");
            uint32_t base = ab + s * TSTAGE;
            uint64_t ad = mk_desc(base);
            uint64_t bd = mk_desc(base + TAB);
            #pragma unroll
            for (int sub = 0; sub < 4; ++sub)
                mma_f16_ss_cg1(tmem, ad + sub * 2, bd + sub * 2, idesc,
                               (ks > 0) || (sub > 0));
            tc_commit(mbs0 + 8 * s);
        }

        if (ks + 3 < nk) {
            const int nxt = (ks + 3) & 3;
            if (ks >= 1) {
                mbar_wait(mbs0 + 8 * nxt, ph[nxt]);
                ph[nxt] ^= 1;
            }
            fill(nxt, ks + 3);
        } else {
            CP_COMMIT();
        }
    }

    {
        const int sl = (nk - 1) & 3;
        mbar_wait(mbs0 + 8 * sl, ph[sl]);
    }
    asm volatile("tcgen05.fence::after_thread_sync;" ::: "memory");
    __syncthreads();

    const int w = tid >> 5, lane = tid & 31;
    if (w < 4) {
        const int row = m0 + w * 32 + lane;
        if (MODE == 0) {
            #pragma unroll
            for (int chunk = 0; chunk < 8; ++chunk) {
                uint32_t dr[32];
                LDTM_X32(dr, tmem + chunk * 32);
                asm volatile("tcgen05.wait::ld.sync.aligned;" ::: "memory");
                const int col0 = n0 + chunk * 32;
                float* Crow = C + (size_t)row * N + col0;
                #pragma unroll
                for (int j = 0; j < 32; j += 4) {
                    float4 v = make_float4(__uint_as_float(dr[j])   + bias[col0 + j],
                                           __uint_as_float(dr[j+1]) + bias[col0 + j + 1],
                                           __uint_as_float(dr[j+2]) + bias[col0 + j + 2],
                                           __uint_as_float(dr[j+3]) + bias[col0 + j + 3]);
                    *(float4*)(Crow + j) = v;
                }
            }
        } else {
            const int part = n0 / CM;
            const int head0 = (n0 % CM) >> 7;
            const int b = row >> 11, tok = row & (NTOK - 1);
            if (part == 2) {
                #pragma unroll
                for (int chunk = 0; chunk < 8; ++chunk) {
                    uint32_t dr[32];
                    LDTM_X32(dr, tmem + chunk * 32);
                    asm volatile("tcgen05.wait::ld.sync.aligned;" ::: "memory");
                    const int col0 = n0 + chunk * 32;
                    const int head = head0 + (chunk >> 2), d0 = (chunk & 3) * 32;
                    __half* dst = g_v16 +
                        (((size_t)b * HEADS + head) * NTOK + tok) * DHEAD + d0;
                    #pragma unroll
                    for (int j = 0; j < 32; j += 2)
                        *(__half2*)(dst + j) = __floats2half2_rn(
                            __uint_as_float(dr[j])   + bias[col0 + j],
                            __uint_as_float(dr[j+1]) + bias[col0 + j + 1]);
                }
            } else {
                const float* ws = (part == 0) ? wsm : wsm + 128;
                const float sc = (part == 0) ? 0.08838834764831845f : 1.0f;
                __half* dstb = (part == 0) ? g_q16 : g_k16;
                #pragma unroll
                for (int hh = 0; hh < 2; ++hh) {
                    float x[128];
                    #pragma unroll
                    for (int c4 = 0; c4 < 4; ++c4) {
                        uint32_t* xr = (uint32_t*)&x[c4 * 32];
                        LDTM_X32(xr, tmem + (hh * 4 + c4) * 32);
                        asm volatile("tcgen05.wait::ld.sync.aligned;" ::: "memory");
                        const int col0 = n0 + (hh * 4 + c4) * 32;
                        #pragma unroll
                        for (int j = 0; j < 32; ++j)
                            x[c4 * 32 + j] = __uint_as_float(xr[j]) + bias[col0 + j];
                    }
                    float ss = 0.f;
                    #pragma unroll
                    for (int j = 0; j < 128; ++j) ss += x[j] * x[j];
                    const float rn = rsqrtf(ss * (1.f / DHEAD) + 1e-6f);
                    __half* dst = dstb +
                        (((size_t)b * HEADS + head0 + hh) * NTOK + tok) * DHEAD;
                    const float2* rt = g_rtab + (size_t)tok * 64;
                    #pragma unroll
                    for (int p = 0; p < 64; ++p) {
                        float2 t = rt[p];
                        float y0 = x[2*p]     * rn * ws[2*p];
                        float y1 = x[2*p + 1] * rn * ws[2*p + 1];
                        float o0 = (y0 * t.x - y1 * t.y) * sc;
                        float o1 = (y1 * t.x + y0 * t.y) * sc;
                        *(__half2*)(dst + 2*p) = __floats2half2_rn(o0, o1);
                    }
                }
            }
        }
    }
    __syncthreads();
    if (tid < 32) {
        asm volatile("tcgen05.relinquish_alloc_permit.cta_group::1.sync.aligned;");
        asm volatile("tcgen05.dealloc.cta_group::1.sync.aligned.b32 %0, %1;"
                     :: "r"(tmem), "r"(256u));
    }

#else
    // -------- mma.sync fallback (compile-validity on non-'a' passes only) ---
    __half* sh = (__half*)ts;
    const int lane = tid & 31, warp = tid >> 5;
    const int g = lane >> 2, cq = lane & 3;
    const int wm = warp >> 2, wn = warp & 3;
    const int GST = 128 * 40, GSTG = 2 * GST;

    for (int half = 0; half < 2; ++half) {
        const int nh0 = n0 + half * 128;
        const int lrow = tid >> 2, lch = tid & 3;
        const __half* Ag = A + (size_t)(m0 + lrow) * K + lch * 8;
        const __half* Bg = B + (size_t)(nh0 + lrow) * K + lch * 8;

        float acc[4][4][4] = {};

        auto issue = [&](int s, int k0) {
            __half* As = sh + s * GSTG;
            __half* Bs = As + GST;
            uint32_t da = smaddr(As + lrow * 40 + lch * 8);
            uint32_t db = smaddr(Bs + lrow * 40 + lch * 8);
            cpa16(da,            Ag + k0);
            cpa16(da + 64*40*2,  Ag + (size_t)64 * K + k0);
            cpa16(db,            Bg + k0);
            cpa16(db + 64*40*2,  Bg + (size_t)64 * K + k0);
        };

        issue(0, 0);  CP_COMMIT();
        issue(1, 32); CP_COMMIT();
        issue(2, 64); CP_COMMIT();

        const int nk32 = K / 32;
        for (int ks = 0; ks < nk32; ++ks) {
            if (ks == nk32 - 1) { CP_WAIT(0); } else { CP_WAIT(1); }
            __syncthreads();
            if (ks + 3 < nk32) issue((ks + 3) & 3, (ks + 3) * 32);
            CP_COMMIT();

            const __half* As = sh + (ks & 3) * GSTG;
            const __half* Bs = As + GST;
            #pragma unroll
            for (int kk = 0; kk < 2; ++kk) {
                uint32_t af[4][4], bf[4][2];
                #pragma unroll
                for (int mt = 0; mt < 4; ++mt)
                    ldsm4(af[mt][0], af[mt][1], af[mt][2], af[mt][3],
                          smaddr(As + (wm*64 + mt*16 + (lane & 15)) * 40
                                    + kk*16 + (lane >> 4) * 8));
                #pragma unroll
                for (int p = 0; p < 2; ++p)
                    ldsm4(bf[2*p][0], bf[2*p+1][0], bf[2*p][1], bf[2*p+1][1],
                          smaddr(Bs + (wn*32 + p*16 + (lane & 15)) * 40
                                    + kk*16 + (lane >> 4) * 8));
                #pragma unroll
                for (int mt = 0; mt < 4; ++mt)
                    #pragma unroll
                    for (int nt = 0; nt < 4; ++nt)
                        mma16(acc[mt][nt], af[mt], bf[nt]);
            }
            __syncthreads();
        }

        #pragma unroll
        for (int mt = 0; mt < 4; ++mt) {
            int r0 = m0 + wm*64 + mt*16 + g;
            int r1 = r0 + 8;
            #pragma unroll
            for (int nt = 0; nt < 4; ++nt) {
                int col = nh0 + wn*32 + nt*8 + 2*cq;
                float b0 = bias[col], b1 = bias[col + 1];
                float2 v0 = make_float2(acc[mt][nt][0] + b0, acc[mt][nt][1] + b1);
                float2 v1 = make_float2(acc[mt][nt][2] + b0, acc[mt][nt][3] + b1);
                if (MODE == 0) {
                    *(float2*)(C + (size_t)r0 * N + col) = v0;
                    *(float2*)(C + (size_t)r1 * N + col) = v1;
                } else {
                    int part = col / CM;
                    int within = col % CM;
                    int head = within >> 7;
                    int d = within & 127;
                    int b0i = r0 >> 11, t0 = r0 & (NTOK - 1);
                    int b1i = r1 >> 11, t1 = r1 & (NTOK - 1);
                    size_t o0 = (((size_t)b0i * HEADS + head) * NTOK + t0) * DHEAD + d;
                    size_t o1 = (((size_t)b1i * HEADS + head) * NTOK + t1) * DHEAD + d;
                    if (part == 0) {
                        *(float2*)(g_q + o0) = v0; *(float2*)(g_q + o1) = v1;
                    } else if (part == 1) {
                        *(float2*)(g_k + o0) = v0; *(float2*)(g_k + o1) = v1;
                    } else {
                        *(__half2*)(g_v16 + o0) = __floats2half2_rn(v0.x, v0.y);
                        *(__half2*)(g_v16 + o1) = __floats2half2_rn(v1.x, v1.y);
                    }
                }
            }
        }
        __syncthreads();
    }
#endif
}

// ---------------------------------------------------------------------------
// Flash attention, fp16 mma.sync. Br=128 (8 warps x 16 rows), Bc=64.
// No-max softmax (s <= sqrt(128), p = exp2(s*log2e - 8) — shift-exact).
// Single barrier per chunk: compute c -> issue c+2 -> CP_WAIT(1) -> barrier
// (provides chunk c+1 visibility AND the stage anti-dependency).
// 3-stage K/V cp.async pipeline (104 KB smem).
// ---------------------------------------------------------------------------
#define FKV 8704                // 64*136 halves
#define FSTG (2 * FKV)          // K+V per stage (halves)
#define FLASH_SMEM (3 * FSTG * 2)   // 104448 B
#define L2E 1.4426950408889634f

__global__ __launch_bounds__(256, 1)
void flash_h()
{
    extern __shared__ __half fsh[];

    const int tid = threadIdx.x, lane = tid & 31, w = tid >> 5;
    const int g = lane >> 2, cq = lane & 3;
    const int q0 = blockIdx.x * 128;
    const size_t hb = ((size_t)blockIdx.z * HEADS + blockIdx.y) * NTOK * DHEAD;
    const __half* Qg = g_q16 + hb + (size_t)q0 * DHEAD;
    const __half* Kg = g_k16 + hb;
    const __half* Vg = g_v16 + hb;

    {   // stage Q through stage-0 area, pull register fragments
        #pragma unroll
        for (int it = 0; it < 8; ++it) {
            int cid = it * 256 + tid;
            int r = cid >> 4, ch = cid & 15;
            *(uint4*)(fsh + r * 136 + ch * 8) = *(const uint4*)(Qg + r * 128 + ch * 8);
        }
    }
    __syncthreads();
    uint32_t qa[8][4];
    #pragma unroll
    for (int kk = 0; kk < 8; ++kk)
        ldsm4(qa[kk][0], qa[kk][1], qa[kk][2], qa[kk][3],
              smaddr(fsh + (w*16 + (lane & 15)) * 136 + kk*16 + (lane >> 4) * 8));
    __syncthreads();

    auto issueKV = [&](int s, int c0) {
        __half* Kst = fsh + s * FSTG;
        __half* Vst = Kst + FKV;
        const __half* Kp = Kg + (size_t)c0 * 64 * DHEAD;
        const __half* Vp = Vg + (size_t)c0 * 64 * DHEAD;
        #pragma unroll
        for (int it = 0; it < 4; ++it) {
            int cid = it * 256 + tid;
            int r = cid >> 4, ch = cid & 15;
            cpa16(smaddr(Kst + r * 136 + ch * 8), Kp + r * 128 + ch * 8);
            cpa16(smaddr(Vst + r * 136 + ch * 8), Vp + r * 128 + ch * 8);
        }
        CP_COMMIT();
    };

    float od[16][4] = {};
    float l0 = 0.f, l1 = 0.f;

    // prologue: groups 0,1 = chunks 0,1; chunk 0 resident + visible
    issueKV(0, 0);
    issueKV(1, 1);
    CP_WAIT(1);
    __syncthreads();

    const int nc = NTOK / 64;   // 32
    for (int c = 0; c < nc; ++c) {
        const __half* Kst = fsh + (c % 3) * FSTG;
        const __half* Vst = Kst + FKV;

        // S = Q.K^T  (chunk c guaranteed visible)
        float s[8][4] = {};
        #pragma unroll
        for (int kk = 0; kk < 8; ++kk) {
            uint32_t bf[8][2];
            #pragma unroll
            for (int p = 0; p < 4; ++p)
                ldsm4(bf[2*p][0], bf[2*p+1][0], bf[2*p][1], bf[2*p+1][1],
                      smaddr(Kst + (p*16 + (lane & 15)) * 136
                                 + kk*16 + (lane >> 4) * 8));
            #pragma unroll
            for (int nt = 0; nt < 8; ++nt)
                mma16(s[nt], qa[kk], bf[nt]);
        }

        // p = exp2(s*log2e - 8); pack straight into A-fragments; partial sums
        uint32_t pa[4][4];
        float rs0 = 0.f, rs1 = 0.f;
        #pragma unroll
        for (int nt = 0; nt < 8; ++nt) {
            float p0 = exp2f(fmaf(s[nt][0], L2E, -8.f));
            float p1 = exp2f(fmaf(s[nt][1], L2E, -8.f));
            float p2 = exp2f(fmaf(s[nt][2], L2E, -8.f));
            float p3 = exp2f(fmaf(s[nt][3], L2E, -8.f));
            rs0 += p0 + p1;
            rs1 += p2 + p3;
            pa[nt >> 1][(nt & 1) * 2]     = h2u(p0, p1);
            pa[nt >> 1][(nt & 1) * 2 + 1] = h2u(p2, p3);
        }
        l0 += rs0;
        l1 += rs1;

        // O += P.V
        #pragma unroll
        for (int k2 = 0; k2 < 4; ++k2) {
            #pragma unroll
            for (int dp = 0; dp < 8; ++dp) {
                uint32_t v0, v1, v2, v3;
                int t = lane >> 3, r = lane & 7;
                ldsm4t(v0, v1, v2, v3,
                       smaddr(Vst + (k2*16 + (t & 1)*8 + r) * 136
                                  + dp*16 + (t >> 1)*8));
                uint32_t b0[2] = {v0, v1}, b1[2] = {v2, v3};
                mma16(od[2*dp],     pa[k2], b0);
                mma16(od[2*dp + 1], pa[k2], b1);
            }
        }

        // issue chunk c+2 (overwrites stage (c+2)%3 = (c-1)%3, whose reads
        // completed before the PREVIOUS iteration's barrier); keep the
        // one-group-per-iter ledger with an empty commit at the tail.
        if (c + 2 < nc) issueKV((c + 2) % 3, c + 2);
        else            CP_COMMIT();
        CP_WAIT(1);     // commits 0..c+2, allow 1 pending -> chunk c+1 arrived
        __syncthreads();   // chunk c+1 visible; reads of chunk c done
    }

    // single cross-lane reduction of l (4 lanes share each row)
    l0 += __shfl_xor_sync(0xffffffffu, l0, 1);
    l0 += __shfl_xor_sync(0xffffffffu, l0, 2);
    l1 += __shfl_xor_sync(0xffffffffu, l1, 1);
    l1 += __shfl_xor_sync(0xffffffffu, l1, 2);

    float inv0 = 1.f / l0, inv1 = 1.f / l1;
    int r0 = q0 + w*16 + g, r1 = r0 + 8;
    size_t base0 = (((size_t)blockIdx.z * NTOK + r0) * HEADS + blockIdx.y) * DHEAD;
    size_t base1 = (((size_t)blockIdx.z * NTOK + r1) * HEADS + blockIdx.y) * DHEAD;
    #pragma unroll
    for (int dt = 0; dt < 16; ++dt) {
        int col = dt*8 + 2*cq;
        *(__half2*)(g_att16 + base0 + col) =
            __floats2half2_rn(od[dt][0] * inv0, od[dt][1] * inv0);
        *(__half2*)(g_att16 + base1 + col) =
            __floats2half2_rn(od[dt][2] * inv1, od[dt][3] * inv1);
    }
}

// ---------------------------------------------------------------------------
extern "C" void kernel_launch(void* const* d_in, const int* in_sizes, int n_in,
                              void* d_out, int out_size)
{
    const float* x      = (const float*)d_in[0];
    const float* qkv_w  = (const float*)d_in[1];
    const float* qkv_b  = (const float*)d_in[2];
    const float* qn_w   = (const float*)d_in[3];
    const float* kn_w   = (const float*)d_in[4];
    const float* proj_w = (const float*)d_in[5];
    const float* proj_b = (const float*)d_in[6];
    float* out = (float*)d_out;

    __half *x16, *w16, *pw16, *att16;
    cudaGetSymbolAddress((void**)&x16,   g_x16);
    cudaGetSymbolAddress((void**)&w16,   g_w16);
    cudaGetSymbolAddress((void**)&pw16,  g_pw16);
    cudaGetSymbolAddress((void**)&att16, g_att16);

    cudaFuncSetAttribute(gemm_u<1>, cudaFuncAttributeMaxDynamicSharedMemorySize, GEMM_SMEM);
    cudaFuncSetAttribute(gemm_u<0>, cudaFuncAttributeMaxDynamicSharedMemorySize, GEMM_SMEM);
    cudaFuncSetAttribute(flash_h, cudaFuncAttributeMaxDynamicSharedMemorySize, FLASH_SMEM);

    // Launch order puts flash in the ncu capture slot (4th launch).
    // 1) x fp32->fp16
    f2h_kernel<<<1024, 256>>>((const float4*)x, (uint4*)x16, MTOT * CM / 8);
    // 2) qkv_w fp32->fp16 + RoPE table (merged)
    f2h_w_rope_kernel<<<WBLK + 512, 256>>>((const float4*)qkv_w, (uint4*)w16,
                                           3 * CM * CM / 8);
    // 3) QKV GEMM (tcgen05) with fused bias+RMSNorm+RoPE epilogue
    gemm_u<1><<<dim3(3 * CM / 256, MTOT / 128), 256, GEMM_SMEM>>>(
        x16, w16, qkv_b, nullptr, 3 * CM, qn_w, kn_w);
    // 4) Flash attention  <-- profiled slot
    flash_h<<<dim3(NTOK / 128, HEADS, BATCH), 256, FLASH_SMEM>>>();
    // 5) proj_w fp32->fp16 (only needed by step 6)
    f2h_kernel<<<1024, 256>>>((const float4*)proj_w, (uint4*)pw16, CM * CM / 8);
    // 6) Output projection (tcgen05)
    gemm_u<0><<<dim3(CM / 256, MTOT / 128), 256, GEMM_SMEM>>>(
        att16, pw16, proj_b, out, CM, nullptr, nullptr);
}